// round 4
// baseline (speedup 1.0000x reference)
#include <cuda_runtime.h>

// Problem dims (fixed)
#define B_NUM 4
#define S_LEN 2048
#define D_DIM 1024
#define H_NUM 16
#define DH 64
#define MROWS (B_NUM * S_LEN)   // 8192

// Scratch: Q, K, V, Z each [B*S, D] fp32 (device globals — no runtime allocation)
__device__ float g_Q[MROWS * D_DIM];
__device__ float g_K[MROWS * D_DIM];
__device__ float g_V[MROWS * D_DIM];
__device__ float g_Z[MROWS * D_DIM];

// ---------------------------------------------------------------------------
// SGEMM: C[M,N] = A[M,K] @ B[K,N] (+ resid), all row-major fp32.
// 128x128 block tile, BK=16, 256 threads, 8x8 per thread.
// M,N,K must be multiples of 128/128/16 (true here: 8192,1024,1024).
// ---------------------------------------------------------------------------
__global__ __launch_bounds__(256) void sgemm128(
    const float* __restrict__ A, const float* __restrict__ B,
    const float* __restrict__ resid, float* __restrict__ C,
    int M, int N, int K)
{
    __shared__ __align__(16) float As[16][128];   // A transposed: As[k][m]
    __shared__ __align__(16) float Bs[16][128];   // Bs[k][n]

    const int tid = threadIdx.x;
    const int tx = tid & 15;          // 0..15 (n sub-tile)
    const int ty = tid >> 4;          // 0..15 (m sub-tile)
    const int cRow = blockIdx.y * 128;
    const int cCol = blockIdx.x * 128;

    float acc[8][8];
#pragma unroll
    for (int i = 0; i < 8; i++)
#pragma unroll
        for (int j = 0; j < 8; j++) acc[i][j] = 0.f;

    const int aRow = tid >> 2;            // 0..63
    const int aCol = (tid & 3) << 2;      // 0,4,8,12
    const int bRow = tid >> 5;            // 0..7
    const int bCol = (tid & 31) << 2;     // 0..124

    for (int k0 = 0; k0 < K; k0 += 16) {
#pragma unroll
        for (int r = 0; r < 2; r++) {
            const float4 a = *(const float4*)&A[(size_t)(cRow + aRow + 64 * r) * K + k0 + aCol];
            As[aCol + 0][aRow + 64 * r] = a.x;
            As[aCol + 1][aRow + 64 * r] = a.y;
            As[aCol + 2][aRow + 64 * r] = a.z;
            As[aCol + 3][aRow + 64 * r] = a.w;
        }
#pragma unroll
        for (int r = 0; r < 2; r++) {
            *(float4*)&Bs[bRow + 8 * r][bCol] =
                *(const float4*)&B[(size_t)(k0 + bRow + 8 * r) * N + cCol + bCol];
        }
        __syncthreads();

#pragma unroll
        for (int kk = 0; kk < 16; kk++) {
            float rm[8], rn[8];
            *(float4*)&rm[0] = *(float4*)&As[kk][ty * 8];
            *(float4*)&rm[4] = *(float4*)&As[kk][ty * 8 + 4];
            *(float4*)&rn[0] = *(float4*)&Bs[kk][tx * 8];
            *(float4*)&rn[4] = *(float4*)&Bs[kk][tx * 8 + 4];
#pragma unroll
            for (int i = 0; i < 8; i++)
#pragma unroll
                for (int j = 0; j < 8; j++)
                    acc[i][j] = fmaf(rm[i], rn[j], acc[i][j]);
        }
        __syncthreads();
    }

#pragma unroll
    for (int i = 0; i < 8; i++) {
        const int row = cRow + ty * 8 + i;
#pragma unroll
        for (int j0 = 0; j0 < 8; j0 += 4) {
            float4 c = make_float4(acc[i][j0], acc[i][j0 + 1], acc[i][j0 + 2], acc[i][j0 + 3]);
            const size_t off = (size_t)row * N + cCol + tx * 8 + j0;
            if (resid) {
                const float4 rr = *(const float4*)&resid[off];
                c.x += rr.x; c.y += rr.y; c.z += rr.z; c.w += rr.w;
            }
            *(float4*)&C[off] = c;
        }
    }
}

// ---------------------------------------------------------------------------
// Flash-style attention, one (b, h, 64-row q tile) per block, 256 threads.
// 64x64 kv tiles, online softmax in registers (row stats replicated across
// the 16 tx lanes via shfl_xor reductions, which stay within 16-lane halves).
// K is staged transposed in smem (width-68 pad); V reuses the same buffer.
// ---------------------------------------------------------------------------
__global__ __launch_bounds__(256) void attn64(
    const float* __restrict__ Q, const float* __restrict__ K,
    const float* __restrict__ V, float* __restrict__ Z)
{
    extern __shared__ __align__(16) float sm[];
    float* sQ  = sm;            // [64][64]
    float* sKV = sm + 4096;     // KT: [d][kj] width 68 / V: [k][dh] width 68
    float* sP  = sm + 8448;     // [64][64]

    const int q0  = blockIdx.x * 64;
    const int h   = blockIdx.y;
    const int b   = blockIdx.z;
    const int tid = threadIdx.x;
    const int tx  = tid & 15;   // k-col / dh-col sub-tile
    const int ty  = tid >> 4;   // q-row sub-tile
    const size_t base = (size_t)b * S_LEN * D_DIM + h * DH;

    const int lr  = tid >> 4;          // loader row 0..15
    const int ld4 = (tid & 15) * 4;    // loader col*4

    const float scale = 0.125f;  // 1/sqrt(64)
#pragma unroll
    for (int r = 0; r < 4; r++) {
        const int row = lr + 16 * r;
        float4 q = *(const float4*)&Q[base + (size_t)(q0 + row) * D_DIM + ld4];
        q.x *= scale; q.y *= scale; q.z *= scale; q.w *= scale;
        *(float4*)&sQ[row * 64 + ld4] = q;
    }

    float m[4], l[4];
    float4 o[4];
#pragma unroll
    for (int i = 0; i < 4; i++) {
        m[i] = -3.0e38f; l[i] = 0.f;
        o[i] = make_float4(0.f, 0.f, 0.f, 0.f);
    }

    for (int kt = 0; kt < S_LEN / 64; kt++) {
        const int k0 = kt * 64;
        __syncthreads();  // prev PV done reading sKV; sQ visible on first iter

        // Stage K tile transposed: sKV[d][kj]
#pragma unroll
        for (int r = 0; r < 4; r++) {
            const int row = lr + 16 * r;  // kj
            const float4 kv = *(const float4*)&K[base + (size_t)(k0 + row) * D_DIM + ld4];
            sKV[(ld4 + 0) * 68 + row] = kv.x;
            sKV[(ld4 + 1) * 68 + row] = kv.y;
            sKV[(ld4 + 2) * 68 + row] = kv.z;
            sKV[(ld4 + 3) * 68 + row] = kv.w;
        }
        __syncthreads();

        // Scores: s[i][j] = sum_d Qs[4ty+i][d] * KT[d][4tx+j]  (Q pre-scaled)
        float s[4][4];
#pragma unroll
        for (int i = 0; i < 4; i++)
#pragma unroll
            for (int j = 0; j < 4; j++) s[i][j] = 0.f;

#pragma unroll
        for (int d4 = 0; d4 < 64; d4 += 4) {
            float4 qv[4], kv[4];
#pragma unroll
            for (int i = 0; i < 4; i++) qv[i] = *(float4*)&sQ[(4 * ty + i) * 64 + d4];
#pragma unroll
            for (int e = 0; e < 4; e++) kv[e] = *(float4*)&sKV[(d4 + e) * 68 + 4 * tx];
#pragma unroll
            for (int i = 0; i < 4; i++) {
                s[i][0] += qv[i].x * kv[0].x + qv[i].y * kv[1].x + qv[i].z * kv[2].x + qv[i].w * kv[3].x;
                s[i][1] += qv[i].x * kv[0].y + qv[i].y * kv[1].y + qv[i].z * kv[2].y + qv[i].w * kv[3].y;
                s[i][2] += qv[i].x * kv[0].z + qv[i].y * kv[1].z + qv[i].z * kv[2].z + qv[i].w * kv[3].z;
                s[i][3] += qv[i].x * kv[0].w + qv[i].y * kv[1].w + qv[i].z * kv[2].w + qv[i].w * kv[3].w;
            }
        }
        __syncthreads();  // everyone done reading KT

        // Stage V tile (natural layout) into the same buffer
#pragma unroll
        for (int r = 0; r < 4; r++) {
            const int row = lr + 16 * r;
            *(float4*)&sKV[row * 68 + ld4] =
                *(const float4*)&V[base + (size_t)(k0 + row) * D_DIM + ld4];
        }

        // Online softmax (register stats; exact-max, sum replicas differ only in rounding)
#pragma unroll
        for (int i = 0; i < 4; i++) {
            float mx = fmaxf(fmaxf(s[i][0], s[i][1]), fmaxf(s[i][2], s[i][3]));
            mx = fmaxf(mx, __shfl_xor_sync(0xffffffffu, mx, 1));
            mx = fmaxf(mx, __shfl_xor_sync(0xffffffffu, mx, 2));
            mx = fmaxf(mx, __shfl_xor_sync(0xffffffffu, mx, 4));
            mx = fmaxf(mx, __shfl_xor_sync(0xffffffffu, mx, 8));
            const float mn = fmaxf(m[i], mx);
            const float alpha = __expf(m[i] - mn);
            const float p0 = __expf(s[i][0] - mn);
            const float p1 = __expf(s[i][1] - mn);
            const float p2 = __expf(s[i][2] - mn);
            const float p3 = __expf(s[i][3] - mn);
            *(float4*)&sP[(4 * ty + i) * 64 + 4 * tx] = make_float4(p0, p1, p2, p3);
            float rs = p0 + p1 + p2 + p3;
            rs += __shfl_xor_sync(0xffffffffu, rs, 1);
            rs += __shfl_xor_sync(0xffffffffu, rs, 2);
            rs += __shfl_xor_sync(0xffffffffu, rs, 4);
            rs += __shfl_xor_sync(0xffffffffu, rs, 8);
            l[i] = l[i] * alpha + rs;
            m[i] = mn;
            o[i].x *= alpha; o[i].y *= alpha; o[i].z *= alpha; o[i].w *= alpha;
        }
        __syncthreads();  // V + P visible

        // O += P @ V
#pragma unroll
        for (int k4 = 0; k4 < 64; k4 += 4) {
            float4 pv[4], vv[4];
#pragma unroll
            for (int i = 0; i < 4; i++) pv[i] = *(float4*)&sP[(4 * ty + i) * 64 + k4];
#pragma unroll
            for (int e = 0; e < 4; e++) vv[e] = *(float4*)&sKV[(k4 + e) * 68 + 4 * tx];
#pragma unroll
            for (int i = 0; i < 4; i++) {
                o[i].x += pv[i].x * vv[0].x + pv[i].y * vv[1].x + pv[i].z * vv[2].x + pv[i].w * vv[3].x;
                o[i].y += pv[i].x * vv[0].y + pv[i].y * vv[1].y + pv[i].z * vv[2].y + pv[i].w * vv[3].y;
                o[i].z += pv[i].x * vv[0].z + pv[i].y * vv[1].z + pv[i].z * vv[2].z + pv[i].w * vv[3].z;
                o[i].w += pv[i].x * vv[0].w + pv[i].y * vv[1].w + pv[i].z * vv[2].w + pv[i].w * vv[3].w;
            }
        }
    }

    // Normalize and write Z (same [B,S,H,DH]-flattened layout as Q/K/V)
#pragma unroll
    for (int i = 0; i < 4; i++) {
        const float inv = 1.f / l[i];
        float4 r = o[i];
        r.x *= inv; r.y *= inv; r.z *= inv; r.w *= inv;
        *(float4*)&Z[base + (size_t)(q0 + 4 * ty + i) * D_DIM + 4 * tx] = r;
    }
}

// ---------------------------------------------------------------------------
// Inputs (metadata order): x, mask(bool, unused), Wq, Wk, Wv, Wout
// ---------------------------------------------------------------------------
extern "C" void kernel_launch(void* const* d_in, const int* in_sizes, int n_in,
                              void* d_out, int out_size)
{
    (void)in_sizes; (void)n_in; (void)out_size;
    const float* x    = (const float*)d_in[0];
    const float* Wq   = (const float*)d_in[2];
    const float* Wk   = (const float*)d_in[3];
    const float* Wv   = (const float*)d_in[4];
    const float* Wout = (const float*)d_in[5];
    float* out = (float*)d_out;

    float *Qp, *Kp, *Vp, *Zp;
    cudaGetSymbolAddress((void**)&Qp, g_Q);
    cudaGetSymbolAddress((void**)&Kp, g_K);
    cudaGetSymbolAddress((void**)&Vp, g_V);
    cudaGetSymbolAddress((void**)&Zp, g_Z);

    const dim3 gg(D_DIM / 128, MROWS / 128);
    sgemm128<<<gg, 256>>>(x, Wq, nullptr, Qp, MROWS, D_DIM, D_DIM);
    sgemm128<<<gg, 256>>>(x, Wk, nullptr, Kp, MROWS, D_DIM, D_DIM);
    sgemm128<<<gg, 256>>>(x, Wv, nullptr, Vp, MROWS, D_DIM, D_DIM);

    const int smem_bytes = (4096 + 64 * 68 + 4096) * (int)sizeof(float);  // 50176
    cudaFuncSetAttribute(attn64, cudaFuncAttributeMaxDynamicSharedMemorySize, smem_bytes);
    attn64<<<dim3(S_LEN / 64, H_NUM, B_NUM), 256, smem_bytes>>>(Qp, Kp, Vp, Zp);

    sgemm128<<<gg, 256>>>(Zp, Wout, x, out, MROWS, D_DIM, D_DIM);
}

// round 7
// speedup vs baseline: 1.4016x; 1.4016x over previous
#include <cuda_runtime.h>
#include <cuda_bf16.h>
#include <stdint.h>

// Problem dims (fixed)
#define B_NUM 4
#define S_LEN 2048
#define D_DIM 1024
#define H_NUM 16
#define DH 64
#define MROWS (B_NUM * S_LEN)   // 8192

// fp32 scratch
__device__ float g_Q[MROWS * D_DIM];
__device__ float g_K[MROWS * D_DIM];
__device__ float g_V[MROWS * D_DIM];
__device__ float g_Z[MROWS * D_DIM];
// bf16 split operands
__device__ __nv_bfloat16 g_xh[MROWS * D_DIM];
__device__ __nv_bfloat16 g_xl[MROWS * D_DIM];
__device__ __nv_bfloat16 g_zh[MROWS * D_DIM];
__device__ __nv_bfloat16 g_zl[MROWS * D_DIM];
// transposed weights [n][k], hi/lo, for Wq,Wk,Wv,Wout
__device__ __nv_bfloat16 g_wth[4][D_DIM * D_DIM];
__device__ __nv_bfloat16 g_wtl[4][D_DIM * D_DIM];

// ---------------------------------------------------------------------------
// Helpers (baseline sm_103 features only: cp.async, ldmatrix, mma.sync)
// ---------------------------------------------------------------------------
__device__ __forceinline__ uint32_t smem_u32(const void* p) {
    uint32_t a;
    asm("{ .reg .u64 t; cvta.to.shared.u64 t, %1; cvt.u32.u64 %0, t; }" : "=r"(a) : "l"(p));
    return a;
}
#define SW128(off) ((off) ^ (((off) >> 3) & 0x70))
__device__ __forceinline__ void cpa16(uint32_t s, const void* g) {
    asm volatile("cp.async.cg.shared.global [%0], [%1], 16;" :: "r"(s), "l"(__cvta_generic_to_global(g)));
}
#define CP_COMMIT() asm volatile("cp.async.commit_group;" ::: "memory")
template <int N> __device__ __forceinline__ void cp_wait() {
    asm volatile("cp.async.wait_group %0;" :: "n"(N) : "memory");
}
__device__ __forceinline__ void ldsm4(uint32_t* r, uint32_t addr) {
    asm volatile("ldmatrix.sync.aligned.m8n8.x4.shared.b16 {%0,%1,%2,%3}, [%4];"
                 : "=r"(r[0]), "=r"(r[1]), "=r"(r[2]), "=r"(r[3]) : "r"(addr));
}
__device__ __forceinline__ void mma_bf16(float* c, const uint32_t* a, uint32_t b0, uint32_t b1) {
    asm volatile("mma.sync.aligned.m16n8k16.row.col.f32.bf16.bf16.f32 "
                 "{%0,%1,%2,%3}, {%4,%5,%6,%7}, {%8,%9}, {%0,%1,%2,%3};"
                 : "+f"(c[0]), "+f"(c[1]), "+f"(c[2]), "+f"(c[3])
                 : "r"(a[0]), "r"(a[1]), "r"(a[2]), "r"(a[3]), "r"(b0), "r"(b1));
}

// ---------------------------------------------------------------------------
// Split / transpose-split conversion kernels
// ---------------------------------------------------------------------------
__global__ void k_split(const float* __restrict__ x, __nv_bfloat16* __restrict__ h,
                        __nv_bfloat16* __restrict__ l, int n) {
    int i = blockIdx.x * blockDim.x + threadIdx.x;
    if (i < n) {
        const float v = x[i];
        const __nv_bfloat16 hh = __float2bfloat16(v);
        h[i] = hh;
        l[i] = __float2bfloat16(v - __bfloat162float(hh));
    }
}
// W [K][N] fp32 -> Th/Tl [N][K] bf16
__global__ void k_tsplit(const float* __restrict__ W, __nv_bfloat16* __restrict__ Th,
                         __nv_bfloat16* __restrict__ Tl) {
    __shared__ float t[32][33];
    const int n0 = blockIdx.x * 32, k0 = blockIdx.y * 32;
    const int x = threadIdx.x, y = threadIdx.y;  // blockDim (32,8)
#pragma unroll
    for (int r = 0; r < 32; r += 8)
        t[y + r][x] = W[(size_t)(k0 + y + r) * D_DIM + n0 + x];
    __syncthreads();
#pragma unroll
    for (int r = 0; r < 32; r += 8) {
        const float v = t[x][y + r];  // = W[k0+x][n0+y+r]
        const __nv_bfloat16 hh = __float2bfloat16(v);
        const size_t off = (size_t)(n0 + y + r) * D_DIM + k0 + x;
        Th[off] = hh;
        Tl[off] = __float2bfloat16(v - __bfloat162float(hh));
    }
}

// ---------------------------------------------------------------------------
// mma.sync split-bf16 GEMM: C[M,N] = Ah*Bh + Ah*Bl + Al*Bh (+resid)
// A split [M][K] bf16, B split [N][K] bf16 (= W^T, K-major), fp32 accum.
// CTA tile 128x128, BK=64, 8 warps (each 32x64), cp.async double buffer.
// Both operands K-major -> plain (non-trans) ldmatrix gives exact fragments.
// ---------------------------------------------------------------------------
#define TILE_M 128
#define TILE_N 128
#define BK 64
#define NITER (D_DIM / BK)          // 16
#define OFF_AH 0
#define OFF_AL 16384
#define OFF_BH 32768
#define OFF_BL 49152
#define STAGE_BYTES 65536           // 64KB
#define GEMM_SMEM (2 * STAGE_BYTES) // 128KB

__device__ __forceinline__ void gemm_loads(
    uint32_t sbase, int tid, int kt, int m0, int n0,
    const __nv_bfloat16* Ah, const __nv_bfloat16* Al,
    const __nv_bfloat16* Bh, const __nv_bfloat16* Bl)
{
    const int k0 = kt * BK;
#pragma unroll
    for (int c = tid; c < 1024; c += 256) {            // 128 rows x 8 16B-chunks
        const int row = c >> 3, kc = c & 7;
        const uint32_t sw = SW128((uint32_t)(row * 128 + kc * 16));
        const size_t ga = (size_t)(m0 + row) * D_DIM + k0 + kc * 8;
        const size_t gb = (size_t)(n0 + row) * D_DIM + k0 + kc * 8;
        cpa16(sbase + OFF_AH + sw, Ah + ga);
        cpa16(sbase + OFF_AL + sw, Al + ga);
        cpa16(sbase + OFF_BH + sw, Bh + gb);
        cpa16(sbase + OFF_BL + sw, Bl + gb);
    }
    CP_COMMIT();
}

__global__ __launch_bounds__(256, 1)
void gemm_mma3(const __nv_bfloat16* __restrict__ Ah, const __nv_bfloat16* __restrict__ Al,
               const __nv_bfloat16* __restrict__ Bh, const __nv_bfloat16* __restrict__ Bl,
               const float* __restrict__ resid, float* __restrict__ C)
{
    extern __shared__ __align__(128) char smem[];
    const uint32_t sb = smem_u32(smem);
    const int tid = threadIdx.x, wid = tid >> 5, lane = tid & 31;
    const int warp_m = wid & 3;        // 4 warps over M: 32 rows each
    const int warp_n = wid >> 2;       // 2 warps over N: 64 cols each
    const int n0 = blockIdx.x * TILE_N;
    const int m0 = blockIdx.y * TILE_M;

    float acc[2][8][4];
#pragma unroll
    for (int mt = 0; mt < 2; mt++)
#pragma unroll
        for (int nt = 0; nt < 8; nt++)
#pragma unroll
            for (int i = 0; i < 4; i++) acc[mt][nt][i] = 0.f;

    gemm_loads(sb, tid, 0, m0, n0, Ah, Al, Bh, Bl);

    // Fragment smem address components (constant across iters except ks)
    const int arow = warp_m * 32 + (lane & 15);          // + mt*16
    const uint32_t acolb = (uint32_t)((lane >> 4) << 4); // +16B for k-high half
    const int brow = warp_n * 64 + ((lane >> 4) << 3) + (lane & 7);  // + p*16
    const uint32_t bcolb = (uint32_t)(((lane >> 3) & 1) << 4);

    for (int it = 0; it < NITER; it++) {
        if (it + 1 < NITER)
            gemm_loads(sb + ((it + 1) & 1) * STAGE_BYTES, tid, it + 1, m0, n0, Ah, Al, Bh, Bl);
        if (it + 1 < NITER) cp_wait<1>(); else cp_wait<0>();
        __syncthreads();

        const uint32_t s0 = sb + (it & 1) * STAGE_BYTES;
#pragma unroll
        for (int ks = 0; ks < 4; ks++) {
            const uint32_t kb = (uint32_t)(ks * 32);
            uint32_t ah[2][4], al[2][4];
#pragma unroll
            for (int mt = 0; mt < 2; mt++) {
                const uint32_t off = SW128((uint32_t)((arow + mt * 16) * 128) + kb + acolb);
                ldsm4(ah[mt], s0 + OFF_AH + off);
                ldsm4(al[mt], s0 + OFF_AL + off);
            }
            uint32_t bh[4][4], bl[4][4];   // [p]: regs {nt=2p b0,b1, nt=2p+1 b0,b1}
#pragma unroll
            for (int p = 0; p < 4; p++) {
                const uint32_t off = SW128((uint32_t)((brow + p * 16) * 128) + kb + bcolb);
                ldsm4(bh[p], s0 + OFF_BH + off);
                ldsm4(bl[p], s0 + OFF_BL + off);
            }
#pragma unroll
            for (int mt = 0; mt < 2; mt++)
#pragma unroll
                for (int p = 0; p < 4; p++)
#pragma unroll
                    for (int hf = 0; hf < 2; hf++) {
                        float* c = acc[mt][p * 2 + hf];
                        mma_bf16(c, ah[mt], bh[p][hf * 2], bh[p][hf * 2 + 1]);
                        mma_bf16(c, ah[mt], bl[p][hf * 2], bl[p][hf * 2 + 1]);
                        mma_bf16(c, al[mt], bh[p][hf * 2], bh[p][hf * 2 + 1]);
                    }
        }
        __syncthreads();
    }

    // Epilogue: fragment (groupID=lane>>2 row, (lane&3)*2 col pairs)
#pragma unroll
    for (int mt = 0; mt < 2; mt++) {
        const int row0 = m0 + warp_m * 32 + mt * 16 + (lane >> 2);
#pragma unroll
        for (int nt = 0; nt < 8; nt++) {
            const int col = n0 + warp_n * 64 + nt * 8 + (lane & 3) * 2;
            const float* c = acc[mt][nt];
            size_t off = (size_t)row0 * D_DIM + col;
            float2 v0 = make_float2(c[0], c[1]);
            float2 v1 = make_float2(c[2], c[3]);
            if (resid) {
                const float2 r0 = *(const float2*)&resid[off];
                const float2 r1 = *(const float2*)&resid[off + 8 * D_DIM];
                v0.x += r0.x; v0.y += r0.y;
                v1.x += r1.x; v1.y += r1.y;
            }
            *(float2*)&C[off] = v0;
            *(float2*)&C[off + 8 * D_DIM] = v1;
        }
    }
}

// ---------------------------------------------------------------------------
// Flash-style attention (unchanged from R4 passing kernel)
// ---------------------------------------------------------------------------
__global__ __launch_bounds__(256) void attn64(
    const float* __restrict__ Q, const float* __restrict__ K,
    const float* __restrict__ V, float* __restrict__ Z)
{
    extern __shared__ __align__(16) float sm[];
    float* sQ  = sm;
    float* sKV = sm + 4096;
    float* sP  = sm + 8448;

    const int q0  = blockIdx.x * 64;
    const int h   = blockIdx.y;
    const int b   = blockIdx.z;
    const int tid = threadIdx.x;
    const int tx  = tid & 15;
    const int ty  = tid >> 4;
    const size_t base = (size_t)b * S_LEN * D_DIM + h * DH;

    const int lr  = tid >> 4;
    const int ld4 = (tid & 15) * 4;

    const float scale = 0.125f;
#pragma unroll
    for (int r = 0; r < 4; r++) {
        const int row = lr + 16 * r;
        float4 q = *(const float4*)&Q[base + (size_t)(q0 + row) * D_DIM + ld4];
        q.x *= scale; q.y *= scale; q.z *= scale; q.w *= scale;
        *(float4*)&sQ[row * 64 + ld4] = q;
    }

    float m[4], l[4];
    float4 o[4];
#pragma unroll
    for (int i = 0; i < 4; i++) {
        m[i] = -3.0e38f; l[i] = 0.f;
        o[i] = make_float4(0.f, 0.f, 0.f, 0.f);
    }

    for (int kt = 0; kt < S_LEN / 64; kt++) {
        const int k0 = kt * 64;
        __syncthreads();

#pragma unroll
        for (int r = 0; r < 4; r++) {
            const int row = lr + 16 * r;
            const float4 kv = *(const float4*)&K[base + (size_t)(k0 + row) * D_DIM + ld4];
            sKV[(ld4 + 0) * 68 + row] = kv.x;
            sKV[(ld4 + 1) * 68 + row] = kv.y;
            sKV[(ld4 + 2) * 68 + row] = kv.z;
            sKV[(ld4 + 3) * 68 + row] = kv.w;
        }
        __syncthreads();

        float s[4][4];
#pragma unroll
        for (int i = 0; i < 4; i++)
#pragma unroll
            for (int j = 0; j < 4; j++) s[i][j] = 0.f;

#pragma unroll
        for (int d4 = 0; d4 < 64; d4 += 4) {
            float4 qv[4], kv[4];
#pragma unroll
            for (int i = 0; i < 4; i++) qv[i] = *(float4*)&sQ[(4 * ty + i) * 64 + d4];
#pragma unroll
            for (int e = 0; e < 4; e++) kv[e] = *(float4*)&sKV[(d4 + e) * 68 + 4 * tx];
#pragma unroll
            for (int i = 0; i < 4; i++) {
                s[i][0] += qv[i].x * kv[0].x + qv[i].y * kv[1].x + qv[i].z * kv[2].x + qv[i].w * kv[3].x;
                s[i][1] += qv[i].x * kv[0].y + qv[i].y * kv[1].y + qv[i].z * kv[2].y + qv[i].w * kv[3].y;
                s[i][2] += qv[i].x * kv[0].z + qv[i].y * kv[1].z + qv[i].z * kv[2].z + qv[i].w * kv[3].z;
                s[i][3] += qv[i].x * kv[0].w + qv[i].y * kv[1].w + qv[i].z * kv[2].w + qv[i].w * kv[3].w;
            }
        }
        __syncthreads();

#pragma unroll
        for (int r = 0; r < 4; r++) {
            const int row = lr + 16 * r;
            *(float4*)&sKV[row * 68 + ld4] =
                *(const float4*)&V[base + (size_t)(k0 + row) * D_DIM + ld4];
        }

#pragma unroll
        for (int i = 0; i < 4; i++) {
            float mx = fmaxf(fmaxf(s[i][0], s[i][1]), fmaxf(s[i][2], s[i][3]));
            mx = fmaxf(mx, __shfl_xor_sync(0xffffffffu, mx, 1));
            mx = fmaxf(mx, __shfl_xor_sync(0xffffffffu, mx, 2));
            mx = fmaxf(mx, __shfl_xor_sync(0xffffffffu, mx, 4));
            mx = fmaxf(mx, __shfl_xor_sync(0xffffffffu, mx, 8));
            const float mn = fmaxf(m[i], mx);
            const float alpha = __expf(m[i] - mn);
            const float p0 = __expf(s[i][0] - mn);
            const float p1 = __expf(s[i][1] - mn);
            const float p2 = __expf(s[i][2] - mn);
            const float p3 = __expf(s[i][3] - mn);
            *(float4*)&sP[(4 * ty + i) * 64 + 4 * tx] = make_float4(p0, p1, p2, p3);
            float rs = p0 + p1 + p2 + p3;
            rs += __shfl_xor_sync(0xffffffffu, rs, 1);
            rs += __shfl_xor_sync(0xffffffffu, rs, 2);
            rs += __shfl_xor_sync(0xffffffffu, rs, 4);
            rs += __shfl_xor_sync(0xffffffffu, rs, 8);
            l[i] = l[i] * alpha + rs;
            m[i] = mn;
            o[i].x *= alpha; o[i].y *= alpha; o[i].z *= alpha; o[i].w *= alpha;
        }
        __syncthreads();

#pragma unroll
        for (int k4 = 0; k4 < 64; k4 += 4) {
            float4 pv[4], vv[4];
#pragma unroll
            for (int i = 0; i < 4; i++) pv[i] = *(float4*)&sP[(4 * ty + i) * 64 + k4];
#pragma unroll
            for (int e = 0; e < 4; e++) vv[e] = *(float4*)&sKV[(k4 + e) * 68 + 4 * tx];
#pragma unroll
            for (int i = 0; i < 4; i++) {
                o[i].x += pv[i].x * vv[0].x + pv[i].y * vv[1].x + pv[i].z * vv[2].x + pv[i].w * vv[3].x;
                o[i].y += pv[i].x * vv[0].y + pv[i].y * vv[1].y + pv[i].z * vv[2].y + pv[i].w * vv[3].y;
                o[i].z += pv[i].x * vv[0].z + pv[i].y * vv[1].z + pv[i].z * vv[2].z + pv[i].w * vv[3].z;
                o[i].w += pv[i].x * vv[0].w + pv[i].y * vv[1].w + pv[i].z * vv[2].w + pv[i].w * vv[3].w;
            }
        }
    }

#pragma unroll
    for (int i = 0; i < 4; i++) {
        const float inv = 1.f / l[i];
        float4 r = o[i];
        r.x *= inv; r.y *= inv; r.z *= inv; r.w *= inv;
        *(float4*)&Z[base + (size_t)(q0 + 4 * ty + i) * D_DIM + 4 * tx] = r;
    }
}

// ---------------------------------------------------------------------------
// Inputs (metadata order): x, mask(bool, unused), Wq, Wk, Wv, Wout
// ---------------------------------------------------------------------------
extern "C" void kernel_launch(void* const* d_in, const int* in_sizes, int n_in,
                              void* d_out, int out_size)
{
    (void)in_sizes; (void)n_in; (void)out_size;
    const float* x    = (const float*)d_in[0];
    const float* Wq   = (const float*)d_in[2];
    const float* Wk   = (const float*)d_in[3];
    const float* Wv   = (const float*)d_in[4];
    const float* Wout = (const float*)d_in[5];
    float* out = (float*)d_out;

    float *Qp, *Kp, *Vp, *Zp;
    cudaGetSymbolAddress((void**)&Qp, g_Q);
    cudaGetSymbolAddress((void**)&Kp, g_K);
    cudaGetSymbolAddress((void**)&Vp, g_V);
    cudaGetSymbolAddress((void**)&Zp, g_Z);
    __nv_bfloat16 *xh, *xl, *zh, *zl, *wth, *wtl;
    cudaGetSymbolAddress((void**)&xh, g_xh);
    cudaGetSymbolAddress((void**)&xl, g_xl);
    cudaGetSymbolAddress((void**)&zh, g_zh);
    cudaGetSymbolAddress((void**)&zl, g_zl);
    cudaGetSymbolAddress((void**)&wth, g_wth);
    cudaGetSymbolAddress((void**)&wtl, g_wtl);

    const int NW = D_DIM * D_DIM;
    const float* Ws[4] = {Wq, Wk, Wv, Wout};

    // 1) split x; transpose+split weights
    k_split<<<(MROWS * D_DIM + 255) / 256, 256>>>(x, xh, xl, MROWS * D_DIM);
    for (int w = 0; w < 4; w++)
        k_tsplit<<<dim3(D_DIM / 32, D_DIM / 32), dim3(32, 8)>>>(Ws[w], wth + (size_t)w * NW, wtl + (size_t)w * NW);

    // 2) QKV projections on mma.sync tensor cores
    cudaFuncSetAttribute(gemm_mma3, cudaFuncAttributeMaxDynamicSharedMemorySize, GEMM_SMEM);
    const dim3 gg(D_DIM / TILE_N, MROWS / TILE_M);   // (8, 64)
    gemm_mma3<<<gg, 256, GEMM_SMEM>>>(xh, xl, wth + 0 * (size_t)NW, wtl + 0 * (size_t)NW, nullptr, Qp);
    gemm_mma3<<<gg, 256, GEMM_SMEM>>>(xh, xl, wth + 1 * (size_t)NW, wtl + 1 * (size_t)NW, nullptr, Kp);
    gemm_mma3<<<gg, 256, GEMM_SMEM>>>(xh, xl, wth + 2 * (size_t)NW, wtl + 2 * (size_t)NW, nullptr, Vp);

    // 3) attention (fp32 flash)
    const int smem_bytes = (4096 + 64 * 68 + 4096) * (int)sizeof(float);  // 50176
    cudaFuncSetAttribute(attn64, cudaFuncAttributeMaxDynamicSharedMemorySize, smem_bytes);
    attn64<<<dim3(S_LEN / 64, H_NUM, B_NUM), 256, smem_bytes>>>(Qp, Kp, Vp, Zp);

    // 4) output projection + residual on mma.sync tensor cores
    k_split<<<(MROWS * D_DIM + 255) / 256, 256>>>(Zp, zh, zl, MROWS * D_DIM);
    gemm_mma3<<<gg, 256, GEMM_SMEM>>>(zh, zl, wth + 3 * (size_t)NW, wtl + 3 * (size_t)NW, x, out);
}

// round 8
// speedup vs baseline: 2.1714x; 1.5492x over previous
#include <cuda_runtime.h>
#include <cuda_bf16.h>
#include <stdint.h>

// Problem dims (fixed)
#define B_NUM 4
#define S_LEN 2048
#define D_DIM 1024
#define H_NUM 16
#define DH 64
#define MROWS (B_NUM * S_LEN)   // 8192

// bf16 split operands (no fp32 scratch needed anymore)
__device__ __nv_bfloat16 g_xh[MROWS * D_DIM];
__device__ __nv_bfloat16 g_xl[MROWS * D_DIM];
__device__ __nv_bfloat16 g_qh[MROWS * D_DIM];
__device__ __nv_bfloat16 g_ql[MROWS * D_DIM];
__device__ __nv_bfloat16 g_kh[MROWS * D_DIM];
__device__ __nv_bfloat16 g_kl[MROWS * D_DIM];
__device__ __nv_bfloat16 g_vh[MROWS * D_DIM];
__device__ __nv_bfloat16 g_vl[MROWS * D_DIM];
__device__ __nv_bfloat16 g_zh[MROWS * D_DIM];
__device__ __nv_bfloat16 g_zl[MROWS * D_DIM];
// transposed weights [n][k], hi/lo, for Wq,Wk,Wv,Wout
__device__ __nv_bfloat16 g_wth[4][D_DIM * D_DIM];
__device__ __nv_bfloat16 g_wtl[4][D_DIM * D_DIM];

// ---------------------------------------------------------------------------
// Helpers (baseline sm_103 features: cp.async, ldmatrix, mma.sync)
// ---------------------------------------------------------------------------
__device__ __forceinline__ uint32_t smem_u32(const void* p) {
    uint32_t a;
    asm("{ .reg .u64 t; cvta.to.shared.u64 t, %1; cvt.u32.u64 %0, t; }" : "=r"(a) : "l"(p));
    return a;
}
#define SW128(off) ((off) ^ (((off) >> 3) & 0x70))
__device__ __forceinline__ void cpa16(uint32_t s, const void* g) {
    asm volatile("cp.async.cg.shared.global [%0], [%1], 16;" :: "r"(s), "l"(__cvta_generic_to_global(g)));
}
#define CP_COMMIT() asm volatile("cp.async.commit_group;" ::: "memory")
template <int N> __device__ __forceinline__ void cp_wait() {
    asm volatile("cp.async.wait_group %0;" :: "n"(N) : "memory");
}
__device__ __forceinline__ void ldsm4(uint32_t* r, uint32_t addr) {
    asm volatile("ldmatrix.sync.aligned.m8n8.x4.shared.b16 {%0,%1,%2,%3}, [%4];"
                 : "=r"(r[0]), "=r"(r[1]), "=r"(r[2]), "=r"(r[3]) : "r"(addr));
}
__device__ __forceinline__ void ldsm4t(uint32_t* r, uint32_t addr) {
    asm volatile("ldmatrix.sync.aligned.m8n8.x4.trans.shared.b16 {%0,%1,%2,%3}, [%4];"
                 : "=r"(r[0]), "=r"(r[1]), "=r"(r[2]), "=r"(r[3]) : "r"(addr));
}
__device__ __forceinline__ void mma_bf16(float* c, const uint32_t* a, uint32_t b0, uint32_t b1) {
    asm volatile("mma.sync.aligned.m16n8k16.row.col.f32.bf16.bf16.f32 "
                 "{%0,%1,%2,%3}, {%4,%5,%6,%7}, {%8,%9}, {%0,%1,%2,%3};"
                 : "+f"(c[0]), "+f"(c[1]), "+f"(c[2]), "+f"(c[3])
                 : "r"(a[0]), "r"(a[1]), "r"(a[2]), "r"(a[3]), "r"(b0), "r"(b1));
}
// Split a float pair into bf16 hi (truncated) packed + lo (RN) packed
__device__ __forceinline__ void split_pack(float x0, float x1, uint32_t& hp, uint32_t& lp) {
    const uint32_t b0 = __float_as_uint(x0), b1 = __float_as_uint(x1);
    hp = __byte_perm(b0, b1, 0x7632);
    const float l0 = x0 - __uint_as_float(b0 & 0xFFFF0000u);
    const float l1 = x1 - __uint_as_float(b1 & 0xFFFF0000u);
    const __nv_bfloat162 lv = __float22bfloat162_rn(make_float2(l0, l1));
    lp = *(const uint32_t*)&lv;
}
// exp2: MUFU path and FMA-pipe poly path (|err| ~ 2.4e-6), y <= 0
__device__ __forceinline__ float ex2_mufu(float y) {
    float r; asm("ex2.approx.f32 %0, %1;" : "=f"(r) : "f"(y)); return r;
}
__device__ __forceinline__ float ex2_poly(float y) {
    y = fmaxf(y, -126.0f);
    const float zb = y + 12582912.0f;            // RN to integer (magic 1.5*2^23)
    const int nb = __float_as_int(zb);
    const float f = y - (zb - 12582912.0f);      // f in [-0.5, 0.5]
    float p = fmaf(f, 0.0013333558f, 0.0096181291f);
    p = fmaf(p, f, 0.0555041087f);
    p = fmaf(p, f, 0.2402265070f);
    p = fmaf(p, f, 0.6931471806f);
    p = fmaf(p, f, 1.0f);
    return p * __int_as_float((nb + (127 - 0x4B400000)) << 23);
}

// ---------------------------------------------------------------------------
// Split / transpose-split conversion kernels
// ---------------------------------------------------------------------------
__global__ void k_split(const float* __restrict__ x, __nv_bfloat16* __restrict__ h,
                        __nv_bfloat16* __restrict__ l, int n) {
    int i = blockIdx.x * blockDim.x + threadIdx.x;
    if (i < n) {
        const float v = x[i];
        const __nv_bfloat16 hh = __float2bfloat16(v);
        h[i] = hh;
        l[i] = __float2bfloat16(v - __bfloat162float(hh));
    }
}
__global__ void k_tsplit(const float* __restrict__ W, __nv_bfloat16* __restrict__ Th,
                         __nv_bfloat16* __restrict__ Tl) {
    __shared__ float t[32][33];
    const int n0 = blockIdx.x * 32, k0 = blockIdx.y * 32;
    const int x = threadIdx.x, y = threadIdx.y;  // blockDim (32,8)
#pragma unroll
    for (int r = 0; r < 32; r += 8)
        t[y + r][x] = W[(size_t)(k0 + y + r) * D_DIM + n0 + x];
    __syncthreads();
#pragma unroll
    for (int r = 0; r < 32; r += 8) {
        const float v = t[x][y + r];
        const __nv_bfloat16 hh = __float2bfloat16(v);
        const size_t off = (size_t)(n0 + y + r) * D_DIM + k0 + x;
        Th[off] = hh;
        Tl[off] = __float2bfloat16(v - __bfloat162float(hh));
    }
}

// ---------------------------------------------------------------------------
// mma.sync split-bf16 GEMM (validated R7). Output: either fp32 (+resid) or
// bf16 hi/lo split pair (for feeding attention / next GEMM).
// ---------------------------------------------------------------------------
#define TILE_M 128
#define TILE_N 128
#define BK 64
#define NITER (D_DIM / BK)          // 16
#define OFF_AH 0
#define OFF_AL 16384
#define OFF_BH 32768
#define OFF_BL 49152
#define STAGE_BYTES 65536
#define GEMM_SMEM (2 * STAGE_BYTES)

__device__ __forceinline__ void gemm_loads(
    uint32_t sbase, int tid, int kt, int m0, int n0,
    const __nv_bfloat16* Ah, const __nv_bfloat16* Al,
    const __nv_bfloat16* Bh, const __nv_bfloat16* Bl)
{
    const int k0 = kt * BK;
#pragma unroll
    for (int c = tid; c < 1024; c += 256) {
        const int row = c >> 3, kc = c & 7;
        const uint32_t sw = SW128((uint32_t)(row * 128 + kc * 16));
        const size_t ga = (size_t)(m0 + row) * D_DIM + k0 + kc * 8;
        const size_t gb = (size_t)(n0 + row) * D_DIM + k0 + kc * 8;
        cpa16(sbase + OFF_AH + sw, Ah + ga);
        cpa16(sbase + OFF_AL + sw, Al + ga);
        cpa16(sbase + OFF_BH + sw, Bh + gb);
        cpa16(sbase + OFF_BL + sw, Bl + gb);
    }
    CP_COMMIT();
}

__global__ __launch_bounds__(256, 1)
void gemm_mma3(const __nv_bfloat16* __restrict__ Ah, const __nv_bfloat16* __restrict__ Al,
               const __nv_bfloat16* __restrict__ Bh, const __nv_bfloat16* __restrict__ Bl,
               const float* __restrict__ resid, float* __restrict__ Cf,
               __nv_bfloat16* __restrict__ Oh, __nv_bfloat16* __restrict__ Ol)
{
    extern __shared__ __align__(128) char smem[];
    const uint32_t sb = smem_u32(smem);
    const int tid = threadIdx.x, wid = tid >> 5, lane = tid & 31;
    const int warp_m = wid & 3;
    const int warp_n = wid >> 2;
    const int n0 = blockIdx.x * TILE_N;
    const int m0 = blockIdx.y * TILE_M;

    float acc[2][8][4];
#pragma unroll
    for (int mt = 0; mt < 2; mt++)
#pragma unroll
        for (int nt = 0; nt < 8; nt++)
#pragma unroll
            for (int i = 0; i < 4; i++) acc[mt][nt][i] = 0.f;

    gemm_loads(sb, tid, 0, m0, n0, Ah, Al, Bh, Bl);

    const int arow = warp_m * 32 + (lane & 15);
    const uint32_t acolb = (uint32_t)((lane >> 4) << 4);
    const int brow = warp_n * 64 + ((lane >> 4) << 3) + (lane & 7);
    const uint32_t bcolb = (uint32_t)(((lane >> 3) & 1) << 4);

    for (int it = 0; it < NITER; it++) {
        if (it + 1 < NITER)
            gemm_loads(sb + ((it + 1) & 1) * STAGE_BYTES, tid, it + 1, m0, n0, Ah, Al, Bh, Bl);
        if (it + 1 < NITER) cp_wait<1>(); else cp_wait<0>();
        __syncthreads();

        const uint32_t s0 = sb + (it & 1) * STAGE_BYTES;
#pragma unroll
        for (int ks = 0; ks < 4; ks++) {
            const uint32_t kb = (uint32_t)(ks * 32);
            uint32_t ah[2][4], al[2][4];
#pragma unroll
            for (int mt = 0; mt < 2; mt++) {
                const uint32_t off = SW128((uint32_t)((arow + mt * 16) * 128) + kb + acolb);
                ldsm4(ah[mt], s0 + OFF_AH + off);
                ldsm4(al[mt], s0 + OFF_AL + off);
            }
            uint32_t bh[4][4], bl[4][4];
#pragma unroll
            for (int p = 0; p < 4; p++) {
                const uint32_t off = SW128((uint32_t)((brow + p * 16) * 128) + kb + bcolb);
                ldsm4(bh[p], s0 + OFF_BH + off);
                ldsm4(bl[p], s0 + OFF_BL + off);
            }
#pragma unroll
            for (int mt = 0; mt < 2; mt++)
#pragma unroll
                for (int p = 0; p < 4; p++)
#pragma unroll
                    for (int hf = 0; hf < 2; hf++) {
                        float* c = acc[mt][p * 2 + hf];
                        mma_bf16(c, ah[mt], bh[p][hf * 2], bh[p][hf * 2 + 1]);
                        mma_bf16(c, ah[mt], bl[p][hf * 2], bl[p][hf * 2 + 1]);
                        mma_bf16(c, al[mt], bh[p][hf * 2], bh[p][hf * 2 + 1]);
                    }
        }
        __syncthreads();
    }

#pragma unroll
    for (int mt = 0; mt < 2; mt++) {
        const int row0 = m0 + warp_m * 32 + mt * 16 + (lane >> 2);
#pragma unroll
        for (int nt = 0; nt < 8; nt++) {
            const int col = n0 + warp_n * 64 + nt * 8 + (lane & 3) * 2;
            const float* c = acc[mt][nt];
            const size_t off = (size_t)row0 * D_DIM + col;
            if (Oh) {
                uint32_t hp, lp;
                split_pack(c[0], c[1], hp, lp);
                *(uint32_t*)&Oh[off] = hp; *(uint32_t*)&Ol[off] = lp;
                split_pack(c[2], c[3], hp, lp);
                *(uint32_t*)&Oh[off + 8 * D_DIM] = hp; *(uint32_t*)&Ol[off + 8 * D_DIM] = lp;
            } else {
                float2 v0 = make_float2(c[0], c[1]);
                float2 v1 = make_float2(c[2], c[3]);
                if (resid) {
                    const float2 r0 = *(const float2*)&resid[off];
                    const float2 r1 = *(const float2*)&resid[off + 8 * D_DIM];
                    v0.x += r0.x; v0.y += r0.y; v1.x += r1.x; v1.y += r1.y;
                }
                *(float2*)&Cf[off] = v0;
                *(float2*)&Cf[off + 8 * D_DIM] = v1;
            }
        }
    }
}

// ---------------------------------------------------------------------------
// Tensor-core flash attention. CTA: 128 q-rows x one (b,h); 8 warps x 16 rows.
// kv tiles of 64. Split-precision QK^T and PV (3 mma each). P stays in regs.
// Hybrid exp: MUFU for 3/8 of values, FMA-pipe poly for 5/8.
// smem: Qh[128][64] Ql | 2 stages x {Kh,Kl,Vh,Vl [64][64]} = 96KB
// ---------------------------------------------------------------------------
#define ATT_SMEM 98304
#define SLOG2E 0.1803368801111204f   // 0.125 * log2(e)
#define NKV (S_LEN / 64)             // 32

__device__ __forceinline__ void attn_kv_load(
    uint32_t sbase, int tid, size_t kvbase, int k0,
    const __nv_bfloat16* kh, const __nv_bfloat16* kl,
    const __nv_bfloat16* vh, const __nv_bfloat16* vl)
{
#pragma unroll
    for (int c = tid; c < 512; c += 256) {
        const int row = c >> 3, ch = c & 7;
        const uint32_t sw = SW128((uint32_t)(row * 128 + ch * 16));
        const size_t g = kvbase + (size_t)(k0 + row) * D_DIM + ch * 8;
        cpa16(sbase + sw, kh + g);
        cpa16(sbase + 8192 + sw, kl + g);
        cpa16(sbase + 16384 + sw, vh + g);
        cpa16(sbase + 24576 + sw, vl + g);
    }
    CP_COMMIT();
}

__global__ __launch_bounds__(256, 1)
void attn_mma(const __nv_bfloat16* __restrict__ qh, const __nv_bfloat16* __restrict__ ql,
              const __nv_bfloat16* __restrict__ kh, const __nv_bfloat16* __restrict__ kl,
              const __nv_bfloat16* __restrict__ vh, const __nv_bfloat16* __restrict__ vl,
              __nv_bfloat16* __restrict__ zh, __nv_bfloat16* __restrict__ zl)
{
    extern __shared__ __align__(128) char smem[];
    const uint32_t sb = smem_u32(smem);
    const int tid = threadIdx.x, wid = tid >> 5, lane = tid & 31;
    const int q0 = blockIdx.x * 128;
    const int h = blockIdx.y, b = blockIdx.z;
    const size_t qbase = ((size_t)(b * S_LEN + q0)) * D_DIM + h * DH;
    const size_t kvbase = ((size_t)b * S_LEN) * D_DIM + h * DH;

    // ---- prologue loads: Q tiles + kv tile 0
#pragma unroll
    for (int c = tid; c < 1024; c += 256) {
        const int row = c >> 3, ch = c & 7;
        const uint32_t sw = SW128((uint32_t)(row * 128 + ch * 16));
        const size_t g = qbase + (size_t)row * D_DIM + ch * 8;
        cpa16(sb + sw, qh + g);
        cpa16(sb + 16384 + sw, ql + g);
    }
    CP_COMMIT();
    attn_kv_load(sb + 32768, tid, kvbase, 0, kh, kl, vh, vl);

    // fragment address components
    const int arow = wid * 16 + (lane & 15);
    const uint32_t acolb = (uint32_t)((lane >> 4) << 4);
    const int bnrow = ((lane >> 4) << 3) + (lane & 7);       // K tile (non-trans B)
    const uint32_t bncol = (uint32_t)(((lane >> 3) & 1) << 4);
    const int vrow = ((lane >> 3) & 1) * 8 + (lane & 7);     // V tile (trans B)
    const uint32_t vcolb = (uint32_t)((lane >> 4) << 4);

    uint32_t qfh[4][4], qfl[4][4];
    float O[8][4];
#pragma unroll
    for (int nt = 0; nt < 8; nt++)
#pragma unroll
        for (int i = 0; i < 4; i++) O[nt][i] = 0.f;
    float m0 = -3.0e38f, m1 = -3.0e38f, l0 = 0.f, l1 = 0.f;

    for (int t = 0; t < NKV; t++) {
        __syncthreads();   // all warps done with the stage about to be overwritten
        if (t + 1 < NKV) {
            attn_kv_load(sb + 32768 + ((t + 1) & 1) * 32768, tid, kvbase, (t + 1) * 64, kh, kl, vh, vl);
            cp_wait<1>();
        } else {
            cp_wait<0>();
        }
        __syncthreads();   // current stage (and Q on t==0) visible

        if (t == 0) {      // hoisted Q fragments (constant across kv tiles)
#pragma unroll
            for (int ks = 0; ks < 4; ks++) {
                const uint32_t off = SW128((uint32_t)(arow * 128) + (uint32_t)(ks * 32) + acolb);
                ldsm4(qfh[ks], sb + off);
                ldsm4(qfl[ks], sb + 16384 + off);
            }
        }

        const uint32_t kbB = sb + 32768 + (t & 1) * 32768;

        // ---- S = Q K^T (split 3-mma), fp32 accum
        float S[8][4];
#pragma unroll
        for (int nt = 0; nt < 8; nt++)
#pragma unroll
            for (int i = 0; i < 4; i++) S[nt][i] = 0.f;
#pragma unroll
        for (int ks = 0; ks < 4; ks++) {
            uint32_t bh_[4][4], bl_[4][4];
#pragma unroll
            for (int p = 0; p < 4; p++) {
                const uint32_t off = SW128((uint32_t)((p * 16 + bnrow) * 128) + (uint32_t)(ks * 32) + bncol);
                ldsm4(bh_[p], kbB + off);
                ldsm4(bl_[p], kbB + 8192 + off);
            }
#pragma unroll
            for (int p = 0; p < 4; p++)
#pragma unroll
                for (int hf = 0; hf < 2; hf++) {
                    float* c = S[p * 2 + hf];
                    mma_bf16(c, qfh[ks], bh_[p][hf * 2], bh_[p][hf * 2 + 1]);
                    mma_bf16(c, qfh[ks], bl_[p][hf * 2], bl_[p][hf * 2 + 1]);
                    mma_bf16(c, qfl[ks], bh_[p][hf * 2], bh_[p][hf * 2 + 1]);
                }
        }

        // ---- online softmax (rows g=lane>>2 and g+8; 4 lanes share a row)
        float mx0 = -3.0e38f, mx1 = -3.0e38f;
#pragma unroll
        for (int nt = 0; nt < 8; nt++) {
            mx0 = fmaxf(mx0, fmaxf(S[nt][0], S[nt][1]));
            mx1 = fmaxf(mx1, fmaxf(S[nt][2], S[nt][3]));
        }
        mx0 = fmaxf(mx0, __shfl_xor_sync(0xffffffffu, mx0, 1));
        mx0 = fmaxf(mx0, __shfl_xor_sync(0xffffffffu, mx0, 2));
        mx1 = fmaxf(mx1, __shfl_xor_sync(0xffffffffu, mx1, 1));
        mx1 = fmaxf(mx1, __shfl_xor_sync(0xffffffffu, mx1, 2));
        const float mn0 = fmaxf(m0, mx0), mn1 = fmaxf(m1, mx1);
        const float a0 = ex2_mufu((m0 - mn0) * SLOG2E);
        const float a1 = ex2_mufu((m1 - mn1) * SLOG2E);
        m0 = mn0; m1 = mn1;

        float s0 = 0.f, s1 = 0.f;
#pragma unroll
        for (int nt = 0; nt < 8; nt++) {
            if (nt < 3) {   // MUFU share (3/8)
                S[nt][0] = ex2_mufu((S[nt][0] - mn0) * SLOG2E);
                S[nt][1] = ex2_mufu((S[nt][1] - mn0) * SLOG2E);
                S[nt][2] = ex2_mufu((S[nt][2] - mn1) * SLOG2E);
                S[nt][3] = ex2_mufu((S[nt][3] - mn1) * SLOG2E);
            } else {        // FMA-pipe poly share (5/8)
                S[nt][0] = ex2_poly((S[nt][0] - mn0) * SLOG2E);
                S[nt][1] = ex2_poly((S[nt][1] - mn0) * SLOG2E);
                S[nt][2] = ex2_poly((S[nt][2] - mn1) * SLOG2E);
                S[nt][3] = ex2_poly((S[nt][3] - mn1) * SLOG2E);
            }
            s0 += S[nt][0] + S[nt][1];
            s1 += S[nt][2] + S[nt][3];
        }
        l0 = l0 * a0 + s0;
        l1 = l1 * a1 + s1;
#pragma unroll
        for (int nt = 0; nt < 8; nt++) {
            O[nt][0] *= a0; O[nt][1] *= a0; O[nt][2] *= a1; O[nt][3] *= a1;
        }

        // ---- P fragments in registers (accumulator layout == A-frag layout)
        uint32_t pfh[4][4], pfl[4][4];
#pragma unroll
        for (int ks = 0; ks < 4; ks++) {
            split_pack(S[2 * ks][0], S[2 * ks][1], pfh[ks][0], pfl[ks][0]);
            split_pack(S[2 * ks][2], S[2 * ks][3], pfh[ks][1], pfl[ks][1]);
            split_pack(S[2 * ks + 1][0], S[2 * ks + 1][1], pfh[ks][2], pfl[ks][2]);
            split_pack(S[2 * ks + 1][2], S[2 * ks + 1][3], pfh[ks][3], pfl[ks][3]);
        }

        // ---- O += P V (split 3-mma); V^T fragments via ldmatrix.trans
#pragma unroll
        for (int ks = 0; ks < 4; ks++) {
            uint32_t vh_[4][4], vl_[4][4];
#pragma unroll
            for (int p = 0; p < 4; p++) {
                const uint32_t off = SW128((uint32_t)((ks * 16 + vrow) * 128) + (uint32_t)(p * 32) + vcolb);
                ldsm4t(vh_[p], kbB + 16384 + off);
                ldsm4t(vl_[p], kbB + 24576 + off);
            }
#pragma unroll
            for (int p = 0; p < 4; p++)
#pragma unroll
                for (int hf = 0; hf < 2; hf++) {
                    float* o = O[p * 2 + hf];
                    mma_bf16(o, pfh[ks], vh_[p][hf * 2], vh_[p][hf * 2 + 1]);
                    mma_bf16(o, pfh[ks], vl_[p][hf * 2], vl_[p][hf * 2 + 1]);
                    mma_bf16(o, pfl[ks], vh_[p][hf * 2], vh_[p][hf * 2 + 1]);
                }
        }
    }

    // ---- epilogue: reduce l across the 4 lanes of each row group, write zh/zl
    l0 += __shfl_xor_sync(0xffffffffu, l0, 1);
    l0 += __shfl_xor_sync(0xffffffffu, l0, 2);
    l1 += __shfl_xor_sync(0xffffffffu, l1, 1);
    l1 += __shfl_xor_sync(0xffffffffu, l1, 2);
    const float inv0 = 1.0f / l0, inv1 = 1.0f / l1;

    const int rowg = b * S_LEN + q0 + wid * 16 + (lane >> 2);
#pragma unroll
    for (int nt = 0; nt < 8; nt++) {
        const int col = h * DH + nt * 8 + (lane & 3) * 2;
        uint32_t hp, lp;
        split_pack(O[nt][0] * inv0, O[nt][1] * inv0, hp, lp);
        size_t off = (size_t)rowg * D_DIM + col;
        *(uint32_t*)&zh[off] = hp; *(uint32_t*)&zl[off] = lp;
        split_pack(O[nt][2] * inv1, O[nt][3] * inv1, hp, lp);
        off += (size_t)8 * D_DIM;
        *(uint32_t*)&zh[off] = hp; *(uint32_t*)&zl[off] = lp;
    }
}

// ---------------------------------------------------------------------------
// Inputs (metadata order): x, mask(bool, unused), Wq, Wk, Wv, Wout
// ---------------------------------------------------------------------------
extern "C" void kernel_launch(void* const* d_in, const int* in_sizes, int n_in,
                              void* d_out, int out_size)
{
    (void)in_sizes; (void)n_in; (void)out_size;
    const float* x    = (const float*)d_in[0];
    const float* Wq   = (const float*)d_in[2];
    const float* Wk   = (const float*)d_in[3];
    const float* Wv   = (const float*)d_in[4];
    const float* Wout = (const float*)d_in[5];
    float* out = (float*)d_out;

    __nv_bfloat16 *xh, *xl, *qh, *ql, *kh, *kl, *vh, *vl, *zh, *zl, *wth, *wtl;
    cudaGetSymbolAddress((void**)&xh, g_xh);
    cudaGetSymbolAddress((void**)&xl, g_xl);
    cudaGetSymbolAddress((void**)&qh, g_qh);
    cudaGetSymbolAddress((void**)&ql, g_ql);
    cudaGetSymbolAddress((void**)&kh, g_kh);
    cudaGetSymbolAddress((void**)&kl, g_kl);
    cudaGetSymbolAddress((void**)&vh, g_vh);
    cudaGetSymbolAddress((void**)&vl, g_vl);
    cudaGetSymbolAddress((void**)&zh, g_zh);
    cudaGetSymbolAddress((void**)&zl, g_zl);
    cudaGetSymbolAddress((void**)&wth, g_wth);
    cudaGetSymbolAddress((void**)&wtl, g_wtl);

    const int NW = D_DIM * D_DIM;
    const float* Ws[4] = {Wq, Wk, Wv, Wout};

    // 1) split x; transpose+split weights
    k_split<<<(MROWS * D_DIM + 255) / 256, 256>>>(x, xh, xl, MROWS * D_DIM);
    for (int w = 0; w < 4; w++)
        k_tsplit<<<dim3(D_DIM / 32, D_DIM / 32), dim3(32, 8)>>>(Ws[w], wth + (size_t)w * NW, wtl + (size_t)w * NW);

    // 2) QKV projections -> bf16 split outputs directly
    cudaFuncSetAttribute(gemm_mma3, cudaFuncAttributeMaxDynamicSharedMemorySize, GEMM_SMEM);
    const dim3 gg(D_DIM / TILE_N, MROWS / TILE_M);
    gemm_mma3<<<gg, 256, GEMM_SMEM>>>(xh, xl, wth + 0 * (size_t)NW, wtl + 0 * (size_t)NW, nullptr, nullptr, qh, ql);
    gemm_mma3<<<gg, 256, GEMM_SMEM>>>(xh, xl, wth + 1 * (size_t)NW, wtl + 1 * (size_t)NW, nullptr, nullptr, kh, kl);
    gemm_mma3<<<gg, 256, GEMM_SMEM>>>(xh, xl, wth + 2 * (size_t)NW, wtl + 2 * (size_t)NW, nullptr, nullptr, vh, vl);

    // 3) tensor-core flash attention -> zh/zl
    cudaFuncSetAttribute(attn_mma, cudaFuncAttributeMaxDynamicSharedMemorySize, ATT_SMEM);
    attn_mma<<<dim3(S_LEN / 128, H_NUM, B_NUM), 256, ATT_SMEM>>>(qh, ql, kh, kl, vh, vl, zh, zl);

    // 4) output projection + residual -> fp32 out
    gemm_mma3<<<gg, 256, GEMM_SMEM>>>(zh, zl, wth + 3 * (size_t)NW, wtl + 3 * (size_t)NW, x, out, nullptr, nullptr);
}

// round 9
// speedup vs baseline: 3.3476x; 1.5417x over previous
#include <cuda_runtime.h>
#include <cuda_bf16.h>
#include <stdint.h>

// Problem dims (fixed)
#define B_NUM 4
#define S_LEN 2048
#define D_DIM 1024
#define H_NUM 16
#define DH 64
#define MROWS (B_NUM * S_LEN)   // 8192

// bf16 split operands
__device__ __nv_bfloat16 g_xh[MROWS * D_DIM];
__device__ __nv_bfloat16 g_xl[MROWS * D_DIM];
__device__ __nv_bfloat16 g_qh[MROWS * D_DIM];
__device__ __nv_bfloat16 g_ql[MROWS * D_DIM];
__device__ __nv_bfloat16 g_kh[MROWS * D_DIM];
__device__ __nv_bfloat16 g_kl[MROWS * D_DIM];
__device__ __nv_bfloat16 g_vh[MROWS * D_DIM];
__device__ __nv_bfloat16 g_vl[MROWS * D_DIM];
__device__ __nv_bfloat16 g_zh[MROWS * D_DIM];
__device__ __nv_bfloat16 g_zl[MROWS * D_DIM];
// transposed weights [n][k], hi/lo, for Wq,Wk,Wv,Wout
__device__ __nv_bfloat16 g_wth[4][D_DIM * D_DIM];
__device__ __nv_bfloat16 g_wtl[4][D_DIM * D_DIM];

// ---------------------------------------------------------------------------
// Helpers (baseline sm_103 features: cp.async, ldmatrix, mma.sync)
// ---------------------------------------------------------------------------
__device__ __forceinline__ uint32_t smem_u32(const void* p) {
    uint32_t a;
    asm("{ .reg .u64 t; cvta.to.shared.u64 t, %1; cvt.u32.u64 %0, t; }" : "=r"(a) : "l"(p));
    return a;
}
#define SW128(off) ((off) ^ (((off) >> 3) & 0x70))
__device__ __forceinline__ void cpa16(uint32_t s, const void* g) {
    asm volatile("cp.async.cg.shared.global [%0], [%1], 16;" :: "r"(s), "l"(__cvta_generic_to_global(g)));
}
#define CP_COMMIT() asm volatile("cp.async.commit_group;" ::: "memory")
template <int N> __device__ __forceinline__ void cp_wait() {
    asm volatile("cp.async.wait_group %0;" :: "n"(N) : "memory");
}
__device__ __forceinline__ void ldsm4(uint32_t* r, uint32_t addr) {
    asm volatile("ldmatrix.sync.aligned.m8n8.x4.shared.b16 {%0,%1,%2,%3}, [%4];"
                 : "=r"(r[0]), "=r"(r[1]), "=r"(r[2]), "=r"(r[3]) : "r"(addr));
}
__device__ __forceinline__ void ldsm4t(uint32_t* r, uint32_t addr) {
    asm volatile("ldmatrix.sync.aligned.m8n8.x4.trans.shared.b16 {%0,%1,%2,%3}, [%4];"
                 : "=r"(r[0]), "=r"(r[1]), "=r"(r[2]), "=r"(r[3]) : "r"(addr));
}
__device__ __forceinline__ void mma_bf16(float* c, const uint32_t* a, uint32_t b0, uint32_t b1) {
    asm volatile("mma.sync.aligned.m16n8k16.row.col.f32.bf16.bf16.f32 "
                 "{%0,%1,%2,%3}, {%4,%5,%6,%7}, {%8,%9}, {%0,%1,%2,%3};"
                 : "+f"(c[0]), "+f"(c[1]), "+f"(c[2]), "+f"(c[3])
                 : "r"(a[0]), "r"(a[1]), "r"(a[2]), "r"(a[3]), "r"(b0), "r"(b1));
}
// Split a float pair into bf16 hi (truncated) packed + lo (RN) packed
__device__ __forceinline__ void split_pack(float x0, float x1, uint32_t& hp, uint32_t& lp) {
    const uint32_t b0 = __float_as_uint(x0), b1 = __float_as_uint(x1);
    hp = __byte_perm(b0, b1, 0x7632);
    const float l0 = x0 - __uint_as_float(b0 & 0xFFFF0000u);
    const float l1 = x1 - __uint_as_float(b1 & 0xFFFF0000u);
    const __nv_bfloat162 lv = __float22bfloat162_rn(make_float2(l0, l1));
    lp = *(const uint32_t*)&lv;
}
__device__ __forceinline__ float ex2_mufu(float y) {
    float r; asm("ex2.approx.f32 %0, %1;" : "=f"(r) : "f"(y)); return r;
}

// ---------------------------------------------------------------------------
// Split / transpose-split conversion kernels
// ---------------------------------------------------------------------------
__global__ void k_split(const float* __restrict__ x, __nv_bfloat16* __restrict__ h,
                        __nv_bfloat16* __restrict__ l, int n) {
    int i = blockIdx.x * blockDim.x + threadIdx.x;
    if (i < n) {
        const float v = x[i];
        const __nv_bfloat16 hh = __float2bfloat16(v);
        h[i] = hh;
        l[i] = __float2bfloat16(v - __bfloat162float(hh));
    }
}
__global__ void k_tsplit(const float* __restrict__ W, __nv_bfloat16* __restrict__ Th,
                         __nv_bfloat16* __restrict__ Tl) {
    __shared__ float t[32][33];
    const int n0 = blockIdx.x * 32, k0 = blockIdx.y * 32;
    const int x = threadIdx.x, y = threadIdx.y;  // blockDim (32,8)
#pragma unroll
    for (int r = 0; r < 32; r += 8)
        t[y + r][x] = W[(size_t)(k0 + y + r) * D_DIM + n0 + x];
    __syncthreads();
#pragma unroll
    for (int r = 0; r < 32; r += 8) {
        const float v = t[x][y + r];
        const __nv_bfloat16 hh = __float2bfloat16(v);
        const size_t off = (size_t)(n0 + y + r) * D_DIM + k0 + x;
        Th[off] = hh;
        Tl[off] = __float2bfloat16(v - __bfloat162float(hh));
    }
}

// ---------------------------------------------------------------------------
// mma.sync split-bf16 GEMM (validated R7/R8) — unchanged.
// ---------------------------------------------------------------------------
#define TILE_M 128
#define TILE_N 128
#define BK 64
#define NITER (D_DIM / BK)          // 16
#define OFF_AH 0
#define OFF_AL 16384
#define OFF_BH 32768
#define OFF_BL 49152
#define STAGE_BYTES 65536
#define GEMM_SMEM (2 * STAGE_BYTES)

__device__ __forceinline__ void gemm_loads(
    uint32_t sbase, int tid, int kt, int m0, int n0,
    const __nv_bfloat16* Ah, const __nv_bfloat16* Al,
    const __nv_bfloat16* Bh, const __nv_bfloat16* Bl)
{
    const int k0 = kt * BK;
#pragma unroll
    for (int c = tid; c < 1024; c += 256) {
        const int row = c >> 3, kc = c & 7;
        const uint32_t sw = SW128((uint32_t)(row * 128 + kc * 16));
        const size_t ga = (size_t)(m0 + row) * D_DIM + k0 + kc * 8;
        const size_t gb = (size_t)(n0 + row) * D_DIM + k0 + kc * 8;
        cpa16(sbase + OFF_AH + sw, Ah + ga);
        cpa16(sbase + OFF_AL + sw, Al + ga);
        cpa16(sbase + OFF_BH + sw, Bh + gb);
        cpa16(sbase + OFF_BL + sw, Bl + gb);
    }
    CP_COMMIT();
}

__global__ __launch_bounds__(256, 1)
void gemm_mma3(const __nv_bfloat16* __restrict__ Ah, const __nv_bfloat16* __restrict__ Al,
               const __nv_bfloat16* __restrict__ Bh, const __nv_bfloat16* __restrict__ Bl,
               const float* __restrict__ resid, float* __restrict__ Cf,
               __nv_bfloat16* __restrict__ Oh, __nv_bfloat16* __restrict__ Ol)
{
    extern __shared__ __align__(128) char smem[];
    const uint32_t sb = smem_u32(smem);
    const int tid = threadIdx.x, wid = tid >> 5, lane = tid & 31;
    const int warp_m = wid & 3;
    const int warp_n = wid >> 2;
    const int n0 = blockIdx.x * TILE_N;
    const int m0 = blockIdx.y * TILE_M;

    float acc[2][8][4];
#pragma unroll
    for (int mt = 0; mt < 2; mt++)
#pragma unroll
        for (int nt = 0; nt < 8; nt++)
#pragma unroll
            for (int i = 0; i < 4; i++) acc[mt][nt][i] = 0.f;

    gemm_loads(sb, tid, 0, m0, n0, Ah, Al, Bh, Bl);

    const int arow = warp_m * 32 + (lane & 15);
    const uint32_t acolb = (uint32_t)((lane >> 4) << 4);
    const int brow = warp_n * 64 + ((lane >> 4) << 3) + (lane & 7);
    const uint32_t bcolb = (uint32_t)(((lane >> 3) & 1) << 4);

    for (int it = 0; it < NITER; it++) {
        if (it + 1 < NITER)
            gemm_loads(sb + ((it + 1) & 1) * STAGE_BYTES, tid, it + 1, m0, n0, Ah, Al, Bh, Bl);
        if (it + 1 < NITER) cp_wait<1>(); else cp_wait<0>();
        __syncthreads();

        const uint32_t s0 = sb + (it & 1) * STAGE_BYTES;
#pragma unroll
        for (int ks = 0; ks < 4; ks++) {
            const uint32_t kb = (uint32_t)(ks * 32);
            uint32_t ah[2][4], al[2][4];
#pragma unroll
            for (int mt = 0; mt < 2; mt++) {
                const uint32_t off = SW128((uint32_t)((arow + mt * 16) * 128) + kb + acolb);
                ldsm4(ah[mt], s0 + OFF_AH + off);
                ldsm4(al[mt], s0 + OFF_AL + off);
            }
            uint32_t bh[4][4], bl[4][4];
#pragma unroll
            for (int p = 0; p < 4; p++) {
                const uint32_t off = SW128((uint32_t)((brow + p * 16) * 128) + kb + bcolb);
                ldsm4(bh[p], s0 + OFF_BH + off);
                ldsm4(bl[p], s0 + OFF_BL + off);
            }
#pragma unroll
            for (int mt = 0; mt < 2; mt++)
#pragma unroll
                for (int p = 0; p < 4; p++)
#pragma unroll
                    for (int hf = 0; hf < 2; hf++) {
                        float* c = acc[mt][p * 2 + hf];
                        mma_bf16(c, ah[mt], bh[p][hf * 2], bh[p][hf * 2 + 1]);
                        mma_bf16(c, ah[mt], bl[p][hf * 2], bl[p][hf * 2 + 1]);
                        mma_bf16(c, al[mt], bh[p][hf * 2], bh[p][hf * 2 + 1]);
                    }
        }
        __syncthreads();
    }

#pragma unroll
    for (int mt = 0; mt < 2; mt++) {
        const int row0 = m0 + warp_m * 32 + mt * 16 + (lane >> 2);
#pragma unroll
        for (int nt = 0; nt < 8; nt++) {
            const int col = n0 + warp_n * 64 + nt * 8 + (lane & 3) * 2;
            const float* c = acc[mt][nt];
            const size_t off = (size_t)row0 * D_DIM + col;
            if (Oh) {
                uint32_t hp, lp;
                split_pack(c[0], c[1], hp, lp);
                *(uint32_t*)&Oh[off] = hp; *(uint32_t*)&Ol[off] = lp;
                split_pack(c[2], c[3], hp, lp);
                *(uint32_t*)&Oh[off + 8 * D_DIM] = hp; *(uint32_t*)&Ol[off + 8 * D_DIM] = lp;
            } else {
                float2 v0 = make_float2(c[0], c[1]);
                float2 v1 = make_float2(c[2], c[3]);
                if (resid) {
                    const float2 r0 = *(const float2*)&resid[off];
                    const float2 r1 = *(const float2*)&resid[off + 8 * D_DIM];
                    v0.x += r0.x; v0.y += r0.y; v1.x += r1.x; v1.y += r1.y;
                }
                *(float2*)&Cf[off] = v0;
                *(float2*)&Cf[off + 8 * D_DIM] = v1;
            }
        }
    }
}

// ---------------------------------------------------------------------------
// Tensor-core flash attention (R8 structure). R9: all-MUFU exp (poly deleted),
// fused scale-FMA into exp arg, ballot-gated O-rescale skip.
// ---------------------------------------------------------------------------
#define ATT_SMEM 98304
#define SLOG2E 0.1803368801111204f   // 0.125 * log2(e)
#define NKV (S_LEN / 64)             // 32

__device__ __forceinline__ void attn_kv_load(
    uint32_t sbase, int tid, size_t kvbase, int k0,
    const __nv_bfloat16* kh, const __nv_bfloat16* kl,
    const __nv_bfloat16* vh, const __nv_bfloat16* vl)
{
#pragma unroll
    for (int c = tid; c < 512; c += 256) {
        const int row = c >> 3, ch = c & 7;
        const uint32_t sw = SW128((uint32_t)(row * 128 + ch * 16));
        const size_t g = kvbase + (size_t)(k0 + row) * D_DIM + ch * 8;
        cpa16(sbase + sw, kh + g);
        cpa16(sbase + 8192 + sw, kl + g);
        cpa16(sbase + 16384 + sw, vh + g);
        cpa16(sbase + 24576 + sw, vl + g);
    }
    CP_COMMIT();
}

__global__ __launch_bounds__(256, 1)
void attn_mma(const __nv_bfloat16* __restrict__ qh, const __nv_bfloat16* __restrict__ ql,
              const __nv_bfloat16* __restrict__ kh, const __nv_bfloat16* __restrict__ kl,
              const __nv_bfloat16* __restrict__ vh, const __nv_bfloat16* __restrict__ vl,
              __nv_bfloat16* __restrict__ zh, __nv_bfloat16* __restrict__ zl)
{
    extern __shared__ __align__(128) char smem[];
    const uint32_t sb = smem_u32(smem);
    const int tid = threadIdx.x, wid = tid >> 5, lane = tid & 31;
    const int q0 = blockIdx.x * 128;
    const int h = blockIdx.y, b = blockIdx.z;
    const size_t qbase = ((size_t)(b * S_LEN + q0)) * D_DIM + h * DH;
    const size_t kvbase = ((size_t)b * S_LEN) * D_DIM + h * DH;

#pragma unroll
    for (int c = tid; c < 1024; c += 256) {
        const int row = c >> 3, ch = c & 7;
        const uint32_t sw = SW128((uint32_t)(row * 128 + ch * 16));
        const size_t g = qbase + (size_t)row * D_DIM + ch * 8;
        cpa16(sb + sw, qh + g);
        cpa16(sb + 16384 + sw, ql + g);
    }
    CP_COMMIT();
    attn_kv_load(sb + 32768, tid, kvbase, 0, kh, kl, vh, vl);

    const int arow = wid * 16 + (lane & 15);
    const uint32_t acolb = (uint32_t)((lane >> 4) << 4);
    const int bnrow = ((lane >> 4) << 3) + (lane & 7);
    const uint32_t bncol = (uint32_t)(((lane >> 3) & 1) << 4);
    const int vrow = ((lane >> 3) & 1) * 8 + (lane & 7);
    const uint32_t vcolb = (uint32_t)((lane >> 4) << 4);

    uint32_t qfh[4][4], qfl[4][4];
    float O[8][4];
#pragma unroll
    for (int nt = 0; nt < 8; nt++)
#pragma unroll
        for (int i = 0; i < 4; i++) O[nt][i] = 0.f;
    float m0 = -1.0e30f, m1 = -1.0e30f, l0 = 0.f, l1 = 0.f;

    for (int t = 0; t < NKV; t++) {
        __syncthreads();
        if (t + 1 < NKV) {
            attn_kv_load(sb + 32768 + ((t + 1) & 1) * 32768, tid, kvbase, (t + 1) * 64, kh, kl, vh, vl);
            cp_wait<1>();
        } else {
            cp_wait<0>();
        }
        __syncthreads();

        if (t == 0) {
#pragma unroll
            for (int ks = 0; ks < 4; ks++) {
                const uint32_t off = SW128((uint32_t)(arow * 128) + (uint32_t)(ks * 32) + acolb);
                ldsm4(qfh[ks], sb + off);
                ldsm4(qfl[ks], sb + 16384 + off);
            }
        }

        const uint32_t kbB = sb + 32768 + (t & 1) * 32768;

        // ---- S = Q K^T (split 3-mma), fp32 accum
        float S[8][4];
#pragma unroll
        for (int nt = 0; nt < 8; nt++)
#pragma unroll
            for (int i = 0; i < 4; i++) S[nt][i] = 0.f;
#pragma unroll
        for (int ks = 0; ks < 4; ks++) {
            uint32_t bh_[4][4], bl_[4][4];
#pragma unroll
            for (int p = 0; p < 4; p++) {
                const uint32_t off = SW128((uint32_t)((p * 16 + bnrow) * 128) + (uint32_t)(ks * 32) + bncol);
                ldsm4(bh_[p], kbB + off);
                ldsm4(bl_[p], kbB + 8192 + off);
            }
#pragma unroll
            for (int p = 0; p < 4; p++)
#pragma unroll
                for (int hf = 0; hf < 2; hf++) {
                    float* c = S[p * 2 + hf];
                    mma_bf16(c, qfh[ks], bh_[p][hf * 2], bh_[p][hf * 2 + 1]);
                    mma_bf16(c, qfh[ks], bl_[p][hf * 2], bl_[p][hf * 2 + 1]);
                    mma_bf16(c, qfl[ks], bh_[p][hf * 2], bh_[p][hf * 2 + 1]);
                }
        }

        // ---- online softmax (all-MUFU exp; scale folded into exp argument)
        float mx0 = -1.0e30f, mx1 = -1.0e30f;
#pragma unroll
        for (int nt = 0; nt < 8; nt++) {
            mx0 = fmaxf(mx0, fmaxf(S[nt][0], S[nt][1]));
            mx1 = fmaxf(mx1, fmaxf(S[nt][2], S[nt][3]));
        }
        mx0 = fmaxf(mx0, __shfl_xor_sync(0xffffffffu, mx0, 1));
        mx0 = fmaxf(mx0, __shfl_xor_sync(0xffffffffu, mx0, 2));
        mx1 = fmaxf(mx1, __shfl_xor_sync(0xffffffffu, mx1, 1));
        mx1 = fmaxf(mx1, __shfl_xor_sync(0xffffffffu, mx1, 2));
        const float mn0 = fmaxf(m0, mx0), mn1 = fmaxf(m1, mx1);
        const float mb0 = mn0 * SLOG2E, mb1 = mn1 * SLOG2E;
        const float a0 = ex2_mufu(fmaf(m0, SLOG2E, -mb0));   // == 1.0f exactly when mn0==m0
        const float a1 = ex2_mufu(fmaf(m1, SLOG2E, -mb1));
        m0 = mn0; m1 = mn1;

        float s0 = 0.f, s1 = 0.f;
#pragma unroll
        for (int nt = 0; nt < 8; nt++) {
            S[nt][0] = ex2_mufu(fmaf(S[nt][0], SLOG2E, -mb0));
            S[nt][1] = ex2_mufu(fmaf(S[nt][1], SLOG2E, -mb0));
            S[nt][2] = ex2_mufu(fmaf(S[nt][2], SLOG2E, -mb1));
            S[nt][3] = ex2_mufu(fmaf(S[nt][3], SLOG2E, -mb1));
            s0 += S[nt][0] + S[nt][1];
            s1 += S[nt][2] + S[nt][3];
        }
        l0 = l0 * a0 + s0;
        l1 = l1 * a1 + s1;

        // Rescale O only when some lane's max actually moved (warp-uniform skip)
        if (__ballot_sync(0xffffffffu, (a0 != 1.0f) || (a1 != 1.0f))) {
#pragma unroll
            for (int nt = 0; nt < 8; nt++) {
                O[nt][0] *= a0; O[nt][1] *= a0; O[nt][2] *= a1; O[nt][3] *= a1;
            }
        }

        // ---- P fragments in registers (accumulator layout == A-frag layout)
        uint32_t pfh[4][4], pfl[4][4];
#pragma unroll
        for (int ks = 0; ks < 4; ks++) {
            split_pack(S[2 * ks][0], S[2 * ks][1], pfh[ks][0], pfl[ks][0]);
            split_pack(S[2 * ks][2], S[2 * ks][3], pfh[ks][1], pfl[ks][1]);
            split_pack(S[2 * ks + 1][0], S[2 * ks + 1][1], pfh[ks][2], pfl[ks][2]);
            split_pack(S[2 * ks + 1][2], S[2 * ks + 1][3], pfh[ks][3], pfl[ks][3]);
        }

        // ---- O += P V (split 3-mma); V^T fragments via ldmatrix.trans
#pragma unroll
        for (int ks = 0; ks < 4; ks++) {
            uint32_t vh_[4][4], vl_[4][4];
#pragma unroll
            for (int p = 0; p < 4; p++) {
                const uint32_t off = SW128((uint32_t)((ks * 16 + vrow) * 128) + (uint32_t)(p * 32) + vcolb);
                ldsm4t(vh_[p], kbB + 16384 + off);
                ldsm4t(vl_[p], kbB + 24576 + off);
            }
#pragma unroll
            for (int p = 0; p < 4; p++)
#pragma unroll
                for (int hf = 0; hf < 2; hf++) {
                    float* o = O[p * 2 + hf];
                    mma_bf16(o, pfh[ks], vh_[p][hf * 2], vh_[p][hf * 2 + 1]);
                    mma_bf16(o, pfh[ks], vl_[p][hf * 2], vl_[p][hf * 2 + 1]);
                    mma_bf16(o, pfl[ks], vh_[p][hf * 2], vh_[p][hf * 2 + 1]);
                }
        }
    }

    // ---- epilogue
    l0 += __shfl_xor_sync(0xffffffffu, l0, 1);
    l0 += __shfl_xor_sync(0xffffffffu, l0, 2);
    l1 += __shfl_xor_sync(0xffffffffu, l1, 1);
    l1 += __shfl_xor_sync(0xffffffffu, l1, 2);
    const float inv0 = 1.0f / l0, inv1 = 1.0f / l1;

    const int rowg = b * S_LEN + q0 + wid * 16 + (lane >> 2);
#pragma unroll
    for (int nt = 0; nt < 8; nt++) {
        const int col = h * DH + nt * 8 + (lane & 3) * 2;
        uint32_t hp, lp;
        split_pack(O[nt][0] * inv0, O[nt][1] * inv0, hp, lp);
        size_t off = (size_t)rowg * D_DIM + col;
        *(uint32_t*)&zh[off] = hp; *(uint32_t*)&zl[off] = lp;
        split_pack(O[nt][2] * inv1, O[nt][3] * inv1, hp, lp);
        off += (size_t)8 * D_DIM;
        *(uint32_t*)&zh[off] = hp; *(uint32_t*)&zl[off] = lp;
    }
}

// ---------------------------------------------------------------------------
// Inputs (metadata order): x, mask(bool, unused), Wq, Wk, Wv, Wout
// ---------------------------------------------------------------------------
extern "C" void kernel_launch(void* const* d_in, const int* in_sizes, int n_in,
                              void* d_out, int out_size)
{
    (void)in_sizes; (void)n_in; (void)out_size;
    const float* x    = (const float*)d_in[0];
    const float* Wq   = (const float*)d_in[2];
    const float* Wk   = (const float*)d_in[3];
    const float* Wv   = (const float*)d_in[4];
    const float* Wout = (const float*)d_in[5];
    float* out = (float*)d_out;

    __nv_bfloat16 *xh, *xl, *qh, *ql, *kh, *kl, *vh, *vl, *zh, *zl, *wth, *wtl;
    cudaGetSymbolAddress((void**)&xh, g_xh);
    cudaGetSymbolAddress((void**)&xl, g_xl);
    cudaGetSymbolAddress((void**)&qh, g_qh);
    cudaGetSymbolAddress((void**)&ql, g_ql);
    cudaGetSymbolAddress((void**)&kh, g_kh);
    cudaGetSymbolAddress((void**)&kl, g_kl);
    cudaGetSymbolAddress((void**)&vh, g_vh);
    cudaGetSymbolAddress((void**)&vl, g_vl);
    cudaGetSymbolAddress((void**)&zh, g_zh);
    cudaGetSymbolAddress((void**)&zl, g_zl);
    cudaGetSymbolAddress((void**)&wth, g_wth);
    cudaGetSymbolAddress((void**)&wtl, g_wtl);

    const int NW = D_DIM * D_DIM;
    const float* Ws[4] = {Wq, Wk, Wv, Wout};

    // 1) split x; transpose+split weights
    k_split<<<(MROWS * D_DIM + 255) / 256, 256>>>(x, xh, xl, MROWS * D_DIM);
    for (int w = 0; w < 4; w++)
        k_tsplit<<<dim3(D_DIM / 32, D_DIM / 32), dim3(32, 8)>>>(Ws[w], wth + (size_t)w * NW, wtl + (size_t)w * NW);

    // 2) QKV projections -> bf16 split outputs directly
    cudaFuncSetAttribute(gemm_mma3, cudaFuncAttributeMaxDynamicSharedMemorySize, GEMM_SMEM);
    const dim3 gg(D_DIM / TILE_N, MROWS / TILE_M);
    gemm_mma3<<<gg, 256, GEMM_SMEM>>>(xh, xl, wth + 0 * (size_t)NW, wtl + 0 * (size_t)NW, nullptr, nullptr, qh, ql);
    gemm_mma3<<<gg, 256, GEMM_SMEM>>>(xh, xl, wth + 1 * (size_t)NW, wtl + 1 * (size_t)NW, nullptr, nullptr, kh, kl);
    gemm_mma3<<<gg, 256, GEMM_SMEM>>>(xh, xl, wth + 2 * (size_t)NW, wtl + 2 * (size_t)NW, nullptr, nullptr, vh, vl);

    // 3) tensor-core flash attention -> zh/zl
    cudaFuncSetAttribute(attn_mma, cudaFuncAttributeMaxDynamicSharedMemorySize, ATT_SMEM);
    attn_mma<<<dim3(S_LEN / 128, H_NUM, B_NUM), 256, ATT_SMEM>>>(qh, ql, kh, kl, vh, vl, zh, zl);

    // 4) output projection + residual -> fp32 out
    gemm_mma3<<<gg, 256, GEMM_SMEM>>>(zh, zl, wth + 3 * (size_t)NW, wtl + 3 * (size_t)NW, x, out, nullptr, nullptr);
}

// round 10
// speedup vs baseline: 3.4405x; 1.0277x over previous
#include <cuda_runtime.h>
#include <cuda_bf16.h>
#include <stdint.h>

// Problem dims (fixed)
#define B_NUM 4
#define S_LEN 2048
#define D_DIM 1024
#define H_NUM 16
#define DH 64
#define MROWS (B_NUM * S_LEN)   // 8192

// bf16 split operands
__device__ __nv_bfloat16 g_xh[MROWS * D_DIM];
__device__ __nv_bfloat16 g_xl[MROWS * D_DIM];
__device__ __nv_bfloat16 g_qh[MROWS * D_DIM];
__device__ __nv_bfloat16 g_ql[MROWS * D_DIM];
__device__ __nv_bfloat16 g_kh[MROWS * D_DIM];
__device__ __nv_bfloat16 g_kl[MROWS * D_DIM];
__device__ __nv_bfloat16 g_vh[MROWS * D_DIM];
__device__ __nv_bfloat16 g_vl[MROWS * D_DIM];
__device__ __nv_bfloat16 g_zh[MROWS * D_DIM];
__device__ __nv_bfloat16 g_zl[MROWS * D_DIM];
// transposed weights [n][k], hi/lo, for Wq,Wk,Wv,Wout (contiguous: rows 0..4095)
__device__ __nv_bfloat16 g_wth[4][D_DIM * D_DIM];
__device__ __nv_bfloat16 g_wtl[4][D_DIM * D_DIM];

// ---------------------------------------------------------------------------
// Helpers
// ---------------------------------------------------------------------------
__device__ __forceinline__ uint32_t smem_u32(const void* p) {
    uint32_t a;
    asm("{ .reg .u64 t; cvta.to.shared.u64 t, %1; cvt.u32.u64 %0, t; }" : "=r"(a) : "l"(p));
    return a;
}
#define SW128(off) ((off) ^ (((off) >> 3) & 0x70))
__device__ __forceinline__ void cpa16(uint32_t s, const void* g) {
    asm volatile("cp.async.cg.shared.global [%0], [%1], 16;" :: "r"(s), "l"(__cvta_generic_to_global(g)));
}
#define CP_COMMIT() asm volatile("cp.async.commit_group;" ::: "memory")
template <int N> __device__ __forceinline__ void cp_wait() {
    asm volatile("cp.async.wait_group %0;" :: "n"(N) : "memory");
}
__device__ __forceinline__ void ldsm4(uint32_t* r, uint32_t addr) {
    asm volatile("ldmatrix.sync.aligned.m8n8.x4.shared.b16 {%0,%1,%2,%3}, [%4];"
                 : "=r"(r[0]), "=r"(r[1]), "=r"(r[2]), "=r"(r[3]) : "r"(addr));
}
__device__ __forceinline__ void ldsm4t(uint32_t* r, uint32_t addr) {
    asm volatile("ldmatrix.sync.aligned.m8n8.x4.trans.shared.b16 {%0,%1,%2,%3}, [%4];"
                 : "=r"(r[0]), "=r"(r[1]), "=r"(r[2]), "=r"(r[3]) : "r"(addr));
}
__device__ __forceinline__ void mma_bf16(float* c, const uint32_t* a, uint32_t b0, uint32_t b1) {
    asm volatile("mma.sync.aligned.m16n8k16.row.col.f32.bf16.bf16.f32 "
                 "{%0,%1,%2,%3}, {%4,%5,%6,%7}, {%8,%9}, {%0,%1,%2,%3};"
                 : "+f"(c[0]), "+f"(c[1]), "+f"(c[2]), "+f"(c[3])
                 : "r"(a[0]), "r"(a[1]), "r"(a[2]), "r"(a[3]), "r"(b0), "r"(b1));
}
__device__ __forceinline__ void split_pack(float x0, float x1, uint32_t& hp, uint32_t& lp) {
    const uint32_t b0 = __float_as_uint(x0), b1 = __float_as_uint(x1);
    hp = __byte_perm(b0, b1, 0x7632);
    const float l0 = x0 - __uint_as_float(b0 & 0xFFFF0000u);
    const float l1 = x1 - __uint_as_float(b1 & 0xFFFF0000u);
    const __nv_bfloat162 lv = __float22bfloat162_rn(make_float2(l0, l1));
    lp = *(const uint32_t*)&lv;
}
__device__ __forceinline__ float ex2_mufu(float y) {
    float r; asm("ex2.approx.f32 %0, %1;" : "=f"(r) : "f"(y)); return r;
}

// ---------------------------------------------------------------------------
// Conversion kernels
// ---------------------------------------------------------------------------
__global__ void k_split(const float* __restrict__ x, __nv_bfloat16* __restrict__ h,
                        __nv_bfloat16* __restrict__ l, int n) {
    int i = blockIdx.x * blockDim.x + threadIdx.x;
    if (i < n) {
        const float v = x[i];
        const __nv_bfloat16 hh = __float2bfloat16(v);
        h[i] = hh;
        l[i] = __float2bfloat16(v - __bfloat162float(hh));
    }
}
// All four weights in one launch: blockIdx.z selects W; out rows offset by z*D.
__global__ void k_tsplit4(const float* __restrict__ W0, const float* __restrict__ W1,
                          const float* __restrict__ W2, const float* __restrict__ W3,
                          __nv_bfloat16* __restrict__ Th, __nv_bfloat16* __restrict__ Tl) {
    __shared__ float t[32][33];
    const int w = blockIdx.z;
    const float* W = (w == 0) ? W0 : (w == 1) ? W1 : (w == 2) ? W2 : W3;
    const size_t obase = (size_t)w * D_DIM * D_DIM;
    const int n0 = blockIdx.x * 32, k0 = blockIdx.y * 32;
    const int x = threadIdx.x, y = threadIdx.y;  // blockDim (32,8)
#pragma unroll
    for (int r = 0; r < 32; r += 8)
        t[y + r][x] = W[(size_t)(k0 + y + r) * D_DIM + n0 + x];
    __syncthreads();
#pragma unroll
    for (int r = 0; r < 32; r += 8) {
        const float v = t[x][y + r];
        const __nv_bfloat16 hh = __float2bfloat16(v);
        const size_t off = obase + (size_t)(n0 + y + r) * D_DIM + k0 + x;
        Th[off] = hh;
        Tl[off] = __float2bfloat16(v - __bfloat162float(hh));
    }
}

// ---------------------------------------------------------------------------
// mma.sync split-bf16 GEMM, 3-stage pipeline, single sync/iter.
// Modes: Cf!=null -> fp32 out (+resid), grid.x covers N=1024.
//        Cf==null -> bf16 split outputs routed by n0>>10 among 3 pairs (QKV).
// ---------------------------------------------------------------------------
#define TILE_M 128
#define TILE_N 128
#define BK 64
#define NITER (D_DIM / BK)          // 16
#define OFF_AH 0
#define OFF_AL 16384
#define OFF_BH 32768
#define OFF_BL 49152
#define STAGE_BYTES 65536
#define GEMM_SMEM (3 * STAGE_BYTES)   // 192KB

__device__ __forceinline__ void gemm_loads(
    uint32_t sbase, int tid, int kt, int m0, int n0,
    const __nv_bfloat16* Ah, const __nv_bfloat16* Al,
    const __nv_bfloat16* Bh, const __nv_bfloat16* Bl)
{
    const int k0 = kt * BK;
#pragma unroll
    for (int c = tid; c < 1024; c += 256) {
        const int row = c >> 3, kc = c & 7;
        const uint32_t sw = SW128((uint32_t)(row * 128 + kc * 16));
        const size_t ga = (size_t)(m0 + row) * D_DIM + k0 + kc * 8;
        const size_t gb = (size_t)(n0 + row) * D_DIM + k0 + kc * 8;
        cpa16(sbase + OFF_AH + sw, Ah + ga);
        cpa16(sbase + OFF_AL + sw, Al + ga);
        cpa16(sbase + OFF_BH + sw, Bh + gb);
        cpa16(sbase + OFF_BL + sw, Bl + gb);
    }
    CP_COMMIT();
}

__global__ __launch_bounds__(256, 1)
void gemm_mma3(const __nv_bfloat16* __restrict__ Ah, const __nv_bfloat16* __restrict__ Al,
               const __nv_bfloat16* __restrict__ Bh, const __nv_bfloat16* __restrict__ Bl,
               const float* __restrict__ resid, float* __restrict__ Cf,
               __nv_bfloat16* __restrict__ O0h, __nv_bfloat16* __restrict__ O0l,
               __nv_bfloat16* __restrict__ O1h, __nv_bfloat16* __restrict__ O1l,
               __nv_bfloat16* __restrict__ O2h, __nv_bfloat16* __restrict__ O2l)
{
    extern __shared__ __align__(128) char smem[];
    const uint32_t sb = smem_u32(smem);
    const int tid = threadIdx.x, wid = tid >> 5, lane = tid & 31;
    const int warp_m = wid & 3;
    const int warp_n = wid >> 2;
    const int n0 = blockIdx.x * TILE_N;     // 0..3071 in QKV mode
    const int m0 = blockIdx.y * TILE_M;

    float acc[2][8][4];
#pragma unroll
    for (int mt = 0; mt < 2; mt++)
#pragma unroll
        for (int nt = 0; nt < 8; nt++)
#pragma unroll
            for (int i = 0; i < 4; i++) acc[mt][nt][i] = 0.f;

    // prologue: stages 0,1
    gemm_loads(sb, tid, 0, m0, n0, Ah, Al, Bh, Bl);
    gemm_loads(sb + STAGE_BYTES, tid, 1, m0, n0, Ah, Al, Bh, Bl);
    cp_wait<1>();
    __syncthreads();

    const int arow = warp_m * 32 + (lane & 15);
    const uint32_t acolb = (uint32_t)((lane >> 4) << 4);
    const int brow = warp_n * 64 + ((lane >> 4) << 3) + (lane & 7);
    const uint32_t bcolb = (uint32_t)(((lane >> 3) & 1) << 4);

    for (int it = 0; it < NITER; it++) {
        if (it + 2 < NITER)
            gemm_loads(sb + ((it + 2) % 3) * STAGE_BYTES, tid, it + 2, m0, n0, Ah, Al, Bh, Bl);

        const uint32_t s0 = sb + (it % 3) * STAGE_BYTES;
#pragma unroll
        for (int ks = 0; ks < 4; ks++) {
            const uint32_t kb = (uint32_t)(ks * 32);
            uint32_t ah[2][4], al[2][4];
#pragma unroll
            for (int mt = 0; mt < 2; mt++) {
                const uint32_t off = SW128((uint32_t)((arow + mt * 16) * 128) + kb + acolb);
                ldsm4(ah[mt], s0 + OFF_AH + off);
                ldsm4(al[mt], s0 + OFF_AL + off);
            }
            uint32_t bh[4][4], bl[4][4];
#pragma unroll
            for (int p = 0; p < 4; p++) {
                const uint32_t off = SW128((uint32_t)((brow + p * 16) * 128) + kb + bcolb);
                ldsm4(bh[p], s0 + OFF_BH + off);
                ldsm4(bl[p], s0 + OFF_BL + off);
            }
#pragma unroll
            for (int mt = 0; mt < 2; mt++)
#pragma unroll
                for (int p = 0; p < 4; p++)
#pragma unroll
                    for (int hf = 0; hf < 2; hf++) {
                        float* c = acc[mt][p * 2 + hf];
                        mma_bf16(c, ah[mt], bh[p][hf * 2], bh[p][hf * 2 + 1]);
                        mma_bf16(c, ah[mt], bl[p][hf * 2], bl[p][hf * 2 + 1]);
                        mma_bf16(c, al[mt], bh[p][hf * 2], bh[p][hf * 2 + 1]);
                    }
        }

        if (it + 2 < NITER) cp_wait<1>(); else cp_wait<0>();
        __syncthreads();
    }

    // epilogue
    const int sel = n0 >> 10;                // QKV routing
    const int nl = n0 & (D_DIM - 1);
    __nv_bfloat16* Oh = (sel == 0) ? O0h : (sel == 1) ? O1h : O2h;
    __nv_bfloat16* Ol = (sel == 0) ? O0l : (sel == 1) ? O1l : O2l;
#pragma unroll
    for (int mt = 0; mt < 2; mt++) {
        const int row0 = m0 + warp_m * 32 + mt * 16 + (lane >> 2);
#pragma unroll
        for (int nt = 0; nt < 8; nt++) {
            const int coll = nl + warp_n * 64 + nt * 8 + (lane & 3) * 2;
            const float* c = acc[mt][nt];
            const size_t off = (size_t)row0 * D_DIM + coll;
            if (Cf) {
                float2 v0 = make_float2(c[0], c[1]);
                float2 v1 = make_float2(c[2], c[3]);
                if (resid) {
                    const float2 r0 = *(const float2*)&resid[off];
                    const float2 r1 = *(const float2*)&resid[off + 8 * D_DIM];
                    v0.x += r0.x; v0.y += r0.y; v1.x += r1.x; v1.y += r1.y;
                }
                *(float2*)&Cf[off] = v0;
                *(float2*)&Cf[off + 8 * D_DIM] = v1;
            } else {
                uint32_t hp, lp;
                split_pack(c[0], c[1], hp, lp);
                *(uint32_t*)&Oh[off] = hp; *(uint32_t*)&Ol[off] = lp;
                split_pack(c[2], c[3], hp, lp);
                *(uint32_t*)&Oh[off + 8 * D_DIM] = hp; *(uint32_t*)&Ol[off + 8 * D_DIM] = lp;
            }
        }
    }
}

// ---------------------------------------------------------------------------
// Tensor-core flash attention, 3-stage kv pipeline, single sync/tile.
// smem: Q 32KB | 3 stages x {Kh,Kl,Vh,Vl [64][64]} 32KB = 128KB
// ---------------------------------------------------------------------------
#define ATT_SMEM 131072
#define SLOG2E 0.1803368801111204f   // 0.125 * log2(e)
#define NKV (S_LEN / 64)             // 32

__device__ __forceinline__ void attn_kv_load(
    uint32_t sbase, int tid, size_t kvbase, int k0,
    const __nv_bfloat16* kh, const __nv_bfloat16* kl,
    const __nv_bfloat16* vh, const __nv_bfloat16* vl)
{
#pragma unroll
    for (int c = tid; c < 512; c += 256) {
        const int row = c >> 3, ch = c & 7;
        const uint32_t sw = SW128((uint32_t)(row * 128 + ch * 16));
        const size_t g = kvbase + (size_t)(k0 + row) * D_DIM + ch * 8;
        cpa16(sbase + sw, kh + g);
        cpa16(sbase + 8192 + sw, kl + g);
        cpa16(sbase + 16384 + sw, vh + g);
        cpa16(sbase + 24576 + sw, vl + g);
    }
    CP_COMMIT();
}

__global__ __launch_bounds__(256, 1)
void attn_mma(const __nv_bfloat16* __restrict__ qh, const __nv_bfloat16* __restrict__ ql,
              const __nv_bfloat16* __restrict__ kh, const __nv_bfloat16* __restrict__ kl,
              const __nv_bfloat16* __restrict__ vh, const __nv_bfloat16* __restrict__ vl,
              __nv_bfloat16* __restrict__ zh, __nv_bfloat16* __restrict__ zl)
{
    extern __shared__ __align__(128) char smem[];
    const uint32_t sb = smem_u32(smem);
    const int tid = threadIdx.x, wid = tid >> 5, lane = tid & 31;
    const int q0 = blockIdx.x * 128;
    const int h = blockIdx.y, b = blockIdx.z;
    const size_t qbase = ((size_t)(b * S_LEN + q0)) * D_DIM + h * DH;
    const size_t kvbase = ((size_t)b * S_LEN) * D_DIM + h * DH;

    // prologue: Q (group 0), kv stages 0,1 (groups 1,2)
#pragma unroll
    for (int c = tid; c < 1024; c += 256) {
        const int row = c >> 3, ch = c & 7;
        const uint32_t sw = SW128((uint32_t)(row * 128 + ch * 16));
        const size_t g = qbase + (size_t)row * D_DIM + ch * 8;
        cpa16(sb + sw, qh + g);
        cpa16(sb + 16384 + sw, ql + g);
    }
    CP_COMMIT();
    attn_kv_load(sb + 32768, tid, kvbase, 0, kh, kl, vh, vl);
    attn_kv_load(sb + 65536, tid, kvbase, 64, kh, kl, vh, vl);
    cp_wait<1>();          // Q + kv0 complete
    __syncthreads();

    const int arow = wid * 16 + (lane & 15);
    const uint32_t acolb = (uint32_t)((lane >> 4) << 4);
    const int bnrow = ((lane >> 4) << 3) + (lane & 7);
    const uint32_t bncol = (uint32_t)(((lane >> 3) & 1) << 4);
    const int vrow = ((lane >> 3) & 1) * 8 + (lane & 7);
    const uint32_t vcolb = (uint32_t)((lane >> 4) << 4);

    // Q fragments (constant across kv tiles)
    uint32_t qfh[4][4], qfl[4][4];
#pragma unroll
    for (int ks = 0; ks < 4; ks++) {
        const uint32_t off = SW128((uint32_t)(arow * 128) + (uint32_t)(ks * 32) + acolb);
        ldsm4(qfh[ks], sb + off);
        ldsm4(qfl[ks], sb + 16384 + off);
    }

    float O[8][4];
#pragma unroll
    for (int nt = 0; nt < 8; nt++)
#pragma unroll
        for (int i = 0; i < 4; i++) O[nt][i] = 0.f;
    float m0 = -1.0e30f, m1 = -1.0e30f, l0 = 0.f, l1 = 0.f;

    for (int t = 0; t < NKV; t++) {
        if (t + 2 < NKV)
            attn_kv_load(sb + 32768 + ((t + 2) % 3) * 32768, tid, kvbase, (t + 2) * 64, kh, kl, vh, vl);

        const uint32_t kbB = sb + 32768 + (t % 3) * 32768;

        // ---- S = Q K^T (split 3-mma), fp32 accum
        float S[8][4];
#pragma unroll
        for (int nt = 0; nt < 8; nt++)
#pragma unroll
            for (int i = 0; i < 4; i++) S[nt][i] = 0.f;
#pragma unroll
        for (int ks = 0; ks < 4; ks++) {
            uint32_t bh_[4][4], bl_[4][4];
#pragma unroll
            for (int p = 0; p < 4; p++) {
                const uint32_t off = SW128((uint32_t)((p * 16 + bnrow) * 128) + (uint32_t)(ks * 32) + bncol);
                ldsm4(bh_[p], kbB + off);
                ldsm4(bl_[p], kbB + 8192 + off);
            }
#pragma unroll
            for (int p = 0; p < 4; p++)
#pragma unroll
                for (int hf = 0; hf < 2; hf++) {
                    float* c = S[p * 2 + hf];
                    mma_bf16(c, qfh[ks], bh_[p][hf * 2], bh_[p][hf * 2 + 1]);
                    mma_bf16(c, qfh[ks], bl_[p][hf * 2], bl_[p][hf * 2 + 1]);
                    mma_bf16(c, qfl[ks], bh_[p][hf * 2], bh_[p][hf * 2 + 1]);
                }
        }

        // ---- online softmax (all-MUFU; scale folded into exp arg)
        float mx0 = -1.0e30f, mx1 = -1.0e30f;
#pragma unroll
        for (int nt = 0; nt < 8; nt++) {
            mx0 = fmaxf(mx0, fmaxf(S[nt][0], S[nt][1]));
            mx1 = fmaxf(mx1, fmaxf(S[nt][2], S[nt][3]));
        }
        mx0 = fmaxf(mx0, __shfl_xor_sync(0xffffffffu, mx0, 1));
        mx0 = fmaxf(mx0, __shfl_xor_sync(0xffffffffu, mx0, 2));
        mx1 = fmaxf(mx1, __shfl_xor_sync(0xffffffffu, mx1, 1));
        mx1 = fmaxf(mx1, __shfl_xor_sync(0xffffffffu, mx1, 2));
        const float mn0 = fmaxf(m0, mx0), mn1 = fmaxf(m1, mx1);
        const float mb0 = mn0 * SLOG2E, mb1 = mn1 * SLOG2E;
        const float a0 = ex2_mufu(fmaf(m0, SLOG2E, -mb0));
        const float a1 = ex2_mufu(fmaf(m1, SLOG2E, -mb1));
        m0 = mn0; m1 = mn1;

        float s0 = 0.f, s1 = 0.f;
#pragma unroll
        for (int nt = 0; nt < 8; nt++) {
            S[nt][0] = ex2_mufu(fmaf(S[nt][0], SLOG2E, -mb0));
            S[nt][1] = ex2_mufu(fmaf(S[nt][1], SLOG2E, -mb0));
            S[nt][2] = ex2_mufu(fmaf(S[nt][2], SLOG2E, -mb1));
            S[nt][3] = ex2_mufu(fmaf(S[nt][3], SLOG2E, -mb1));
            s0 += S[nt][0] + S[nt][1];
            s1 += S[nt][2] + S[nt][3];
        }
        l0 = l0 * a0 + s0;
        l1 = l1 * a1 + s1;

        if (__ballot_sync(0xffffffffu, (a0 != 1.0f) || (a1 != 1.0f))) {
#pragma unroll
            for (int nt = 0; nt < 8; nt++) {
                O[nt][0] *= a0; O[nt][1] *= a0; O[nt][2] *= a1; O[nt][3] *= a1;
            }
        }

        // ---- P fragments in registers
        uint32_t pfh[4][4], pfl[4][4];
#pragma unroll
        for (int ks = 0; ks < 4; ks++) {
            split_pack(S[2 * ks][0], S[2 * ks][1], pfh[ks][0], pfl[ks][0]);
            split_pack(S[2 * ks][2], S[2 * ks][3], pfh[ks][1], pfl[ks][1]);
            split_pack(S[2 * ks + 1][0], S[2 * ks + 1][1], pfh[ks][2], pfl[ks][2]);
            split_pack(S[2 * ks + 1][2], S[2 * ks + 1][3], pfh[ks][3], pfl[ks][3]);
        }

        // ---- O += P V (split 3-mma)
#pragma unroll
        for (int ks = 0; ks < 4; ks++) {
            uint32_t vh_[4][4], vl_[4][4];
#pragma unroll
            for (int p = 0; p < 4; p++) {
                const uint32_t off = SW128((uint32_t)((ks * 16 + vrow) * 128) + (uint32_t)(p * 32) + vcolb);
                ldsm4t(vh_[p], kbB + 16384 + off);
                ldsm4t(vl_[p], kbB + 24576 + off);
            }
#pragma unroll
            for (int p = 0; p < 4; p++)
#pragma unroll
                for (int hf = 0; hf < 2; hf++) {
                    float* o = O[p * 2 + hf];
                    mma_bf16(o, pfh[ks], vh_[p][hf * 2], vh_[p][hf * 2 + 1]);
                    mma_bf16(o, pfh[ks], vl_[p][hf * 2], vl_[p][hf * 2 + 1]);
                    mma_bf16(o, pfl[ks], vh_[p][hf * 2], vh_[p][hf * 2 + 1]);
                }
        }

        if (t + 2 < NKV) cp_wait<1>(); else cp_wait<0>();
        __syncthreads();
    }

    // ---- epilogue
    l0 += __shfl_xor_sync(0xffffffffu, l0, 1);
    l0 += __shfl_xor_sync(0xffffffffu, l0, 2);
    l1 += __shfl_xor_sync(0xffffffffu, l1, 1);
    l1 += __shfl_xor_sync(0xffffffffu, l1, 2);
    const float inv0 = 1.0f / l0, inv1 = 1.0f / l1;

    const int rowg = b * S_LEN + q0 + wid * 16 + (lane >> 2);
#pragma unroll
    for (int nt = 0; nt < 8; nt++) {
        const int col = h * DH + nt * 8 + (lane & 3) * 2;
        uint32_t hp, lp;
        split_pack(O[nt][0] * inv0, O[nt][1] * inv0, hp, lp);
        size_t off = (size_t)rowg * D_DIM + col;
        *(uint32_t*)&zh[off] = hp; *(uint32_t*)&zl[off] = lp;
        split_pack(O[nt][2] * inv1, O[nt][3] * inv1, hp, lp);
        off += (size_t)8 * D_DIM;
        *(uint32_t*)&zh[off] = hp; *(uint32_t*)&zl[off] = lp;
    }
}

// ---------------------------------------------------------------------------
// Inputs (metadata order): x, mask(bool, unused), Wq, Wk, Wv, Wout
// ---------------------------------------------------------------------------
extern "C" void kernel_launch(void* const* d_in, const int* in_sizes, int n_in,
                              void* d_out, int out_size)
{
    (void)in_sizes; (void)n_in; (void)out_size;
    const float* x    = (const float*)d_in[0];
    const float* Wq   = (const float*)d_in[2];
    const float* Wk   = (const float*)d_in[3];
    const float* Wv   = (const float*)d_in[4];
    const float* Wout = (const float*)d_in[5];
    float* out = (float*)d_out;

    __nv_bfloat16 *xh, *xl, *qh, *ql, *kh, *kl, *vh, *vl, *zh, *zl, *wth, *wtl;
    cudaGetSymbolAddress((void**)&xh, g_xh);
    cudaGetSymbolAddress((void**)&xl, g_xl);
    cudaGetSymbolAddress((void**)&qh, g_qh);
    cudaGetSymbolAddress((void**)&ql, g_ql);
    cudaGetSymbolAddress((void**)&kh, g_kh);
    cudaGetSymbolAddress((void**)&kl, g_kl);
    cudaGetSymbolAddress((void**)&vh, g_vh);
    cudaGetSymbolAddress((void**)&vl, g_vl);
    cudaGetSymbolAddress((void**)&zh, g_zh);
    cudaGetSymbolAddress((void**)&zl, g_zl);
    cudaGetSymbolAddress((void**)&wth, g_wth);
    cudaGetSymbolAddress((void**)&wtl, g_wtl);

    const int NW = D_DIM * D_DIM;

    // 1) split x; transpose+split all 4 weights in one launch
    k_split<<<(MROWS * D_DIM + 255) / 256, 256>>>(x, xh, xl, MROWS * D_DIM);
    k_tsplit4<<<dim3(D_DIM / 32, D_DIM / 32, 4), dim3(32, 8)>>>(Wq, Wk, Wv, Wout, wth, wtl);

    // 2) merged QKV projection: one GEMM, N=3072 (wth rows 0..3071 are Wq|Wk|Wv)
    cudaFuncSetAttribute(gemm_mma3, cudaFuncAttributeMaxDynamicSharedMemorySize, GEMM_SMEM);
    gemm_mma3<<<dim3(3 * D_DIM / TILE_N, MROWS / TILE_M), 256, GEMM_SMEM>>>(
        xh, xl, wth, wtl, nullptr, nullptr, qh, ql, kh, kl, vh, vl);

    // 3) tensor-core flash attention -> zh/zl
    cudaFuncSetAttribute(attn_mma, cudaFuncAttributeMaxDynamicSharedMemorySize, ATT_SMEM);
    attn_mma<<<dim3(S_LEN / 128, H_NUM, B_NUM), 256, ATT_SMEM>>>(qh, ql, kh, kl, vh, vl, zh, zl);

    // 4) output projection + residual -> fp32 out
    gemm_mma3<<<dim3(D_DIM / TILE_N, MROWS / TILE_M), 256, GEMM_SMEM>>>(
        zh, zl, wth + 3 * (size_t)NW, wtl + 3 * (size_t)NW, x, out,
        nullptr, nullptr, nullptr, nullptr, nullptr, nullptr);
}

// round 11
// speedup vs baseline: 3.5053x; 1.0188x over previous
#include <cuda_runtime.h>
#include <cuda_bf16.h>
#include <stdint.h>

// Problem dims (fixed)
#define B_NUM 4
#define S_LEN 2048
#define D_DIM 1024
#define H_NUM 16
#define DH 64
#define MROWS (B_NUM * S_LEN)   // 8192

// bf16 split operands
__device__ __nv_bfloat16 g_xh[MROWS * D_DIM];
__device__ __nv_bfloat16 g_xl[MROWS * D_DIM];
__device__ __nv_bfloat16 g_qh[MROWS * D_DIM];
__device__ __nv_bfloat16 g_ql[MROWS * D_DIM];
__device__ __nv_bfloat16 g_kh[MROWS * D_DIM];
__device__ __nv_bfloat16 g_kl[MROWS * D_DIM];
__device__ __nv_bfloat16 g_vh[MROWS * D_DIM];
__device__ __nv_bfloat16 g_vl[MROWS * D_DIM];
__device__ __nv_bfloat16 g_zh[MROWS * D_DIM];
__device__ __nv_bfloat16 g_zl[MROWS * D_DIM];
// transposed weights [n][k], hi/lo, for Wq,Wk,Wv,Wout (contiguous rows 0..4095)
__device__ __nv_bfloat16 g_wth[4][D_DIM * D_DIM];
__device__ __nv_bfloat16 g_wtl[4][D_DIM * D_DIM];

// ---------------------------------------------------------------------------
// Helpers
// ---------------------------------------------------------------------------
__device__ __forceinline__ uint32_t smem_u32(const void* p) {
    uint32_t a;
    asm("{ .reg .u64 t; cvta.to.shared.u64 t, %1; cvt.u32.u64 %0, t; }" : "=r"(a) : "l"(p));
    return a;
}
#define SW128(off) ((off) ^ (((off) >> 3) & 0x70))
__device__ __forceinline__ void cpa16(uint32_t s, const void* g) {
    asm volatile("cp.async.cg.shared.global [%0], [%1], 16;" :: "r"(s), "l"(__cvta_generic_to_global(g)));
}
#define CP_COMMIT() asm volatile("cp.async.commit_group;" ::: "memory")
template <int N> __device__ __forceinline__ void cp_wait() {
    asm volatile("cp.async.wait_group %0;" :: "n"(N) : "memory");
}
__device__ __forceinline__ void ldsm4(uint32_t* r, uint32_t addr) {
    asm volatile("ldmatrix.sync.aligned.m8n8.x4.shared.b16 {%0,%1,%2,%3}, [%4];"
                 : "=r"(r[0]), "=r"(r[1]), "=r"(r[2]), "=r"(r[3]) : "r"(addr));
}
__device__ __forceinline__ void ldsm4t(uint32_t* r, uint32_t addr) {
    asm volatile("ldmatrix.sync.aligned.m8n8.x4.trans.shared.b16 {%0,%1,%2,%3}, [%4];"
                 : "=r"(r[0]), "=r"(r[1]), "=r"(r[2]), "=r"(r[3]) : "r"(addr));
}
__device__ __forceinline__ void mma_bf16(float* c, const uint32_t* a, uint32_t b0, uint32_t b1) {
    asm volatile("mma.sync.aligned.m16n8k16.row.col.f32.bf16.bf16.f32 "
                 "{%0,%1,%2,%3}, {%4,%5,%6,%7}, {%8,%9}, {%0,%1,%2,%3};"
                 : "+f"(c[0]), "+f"(c[1]), "+f"(c[2]), "+f"(c[3])
                 : "r"(a[0]), "r"(a[1]), "r"(a[2]), "r"(a[3]), "r"(b0), "r"(b1));
}
__device__ __forceinline__ void split_pack(float x0, float x1, uint32_t& hp, uint32_t& lp) {
    const uint32_t b0 = __float_as_uint(x0), b1 = __float_as_uint(x1);
    hp = __byte_perm(b0, b1, 0x7632);
    const float l0 = x0 - __uint_as_float(b0 & 0xFFFF0000u);
    const float l1 = x1 - __uint_as_float(b1 & 0xFFFF0000u);
    const __nv_bfloat162 lv = __float22bfloat162_rn(make_float2(l0, l1));
    lp = *(const uint32_t*)&lv;
}
__device__ __forceinline__ float ex2_mufu(float y) {
    float r; asm("ex2.approx.f32 %0, %1;" : "=f"(r) : "f"(y)); return r;
}

// ---------------------------------------------------------------------------
// Conversion kernels
// ---------------------------------------------------------------------------
__global__ void k_split(const float* __restrict__ x, __nv_bfloat16* __restrict__ h,
                        __nv_bfloat16* __restrict__ l, int n) {
    int i = blockIdx.x * blockDim.x + threadIdx.x;
    if (i < n) {
        const float v = x[i];
        const __nv_bfloat16 hh = __float2bfloat16(v);
        h[i] = hh;
        l[i] = __float2bfloat16(v - __bfloat162float(hh));
    }
}
__global__ void k_tsplit4(const float* __restrict__ W0, const float* __restrict__ W1,
                          const float* __restrict__ W2, const float* __restrict__ W3,
                          __nv_bfloat16* __restrict__ Th, __nv_bfloat16* __restrict__ Tl) {
    __shared__ float t[32][33];
    const int w = blockIdx.z;
    const float* W = (w == 0) ? W0 : (w == 1) ? W1 : (w == 2) ? W2 : W3;
    const size_t obase = (size_t)w * D_DIM * D_DIM;
    const int n0 = blockIdx.x * 32, k0 = blockIdx.y * 32;
    const int x = threadIdx.x, y = threadIdx.y;  // blockDim (32,8)
#pragma unroll
    for (int r = 0; r < 32; r += 8)
        t[y + r][x] = W[(size_t)(k0 + y + r) * D_DIM + n0 + x];
    __syncthreads();
#pragma unroll
    for (int r = 0; r < 32; r += 8) {
        const float v = t[x][y + r];
        const __nv_bfloat16 hh = __float2bfloat16(v);
        const size_t off = obase + (size_t)(n0 + y + r) * D_DIM + k0 + x;
        Th[off] = hh;
        Tl[off] = __float2bfloat16(v - __bfloat162float(hh));
    }
}

// ---------------------------------------------------------------------------
// mma.sync split-bf16 GEMM, 3-stage pipeline (validated R10) — unchanged.
// ---------------------------------------------------------------------------
#define TILE_M 128
#define TILE_N 128
#define BK 64
#define NITER (D_DIM / BK)          // 16
#define OFF_AH 0
#define OFF_AL 16384
#define OFF_BH 32768
#define OFF_BL 49152
#define STAGE_BYTES 65536
#define GEMM_SMEM (3 * STAGE_BYTES)   // 192KB

__device__ __forceinline__ void gemm_loads(
    uint32_t sbase, int tid, int kt, int m0, int n0,
    const __nv_bfloat16* Ah, const __nv_bfloat16* Al,
    const __nv_bfloat16* Bh, const __nv_bfloat16* Bl)
{
    const int k0 = kt * BK;
#pragma unroll
    for (int c = tid; c < 1024; c += 256) {
        const int row = c >> 3, kc = c & 7;
        const uint32_t sw = SW128((uint32_t)(row * 128 + kc * 16));
        const size_t ga = (size_t)(m0 + row) * D_DIM + k0 + kc * 8;
        const size_t gb = (size_t)(n0 + row) * D_DIM + k0 + kc * 8;
        cpa16(sbase + OFF_AH + sw, Ah + ga);
        cpa16(sbase + OFF_AL + sw, Al + ga);
        cpa16(sbase + OFF_BH + sw, Bh + gb);
        cpa16(sbase + OFF_BL + sw, Bl + gb);
    }
    CP_COMMIT();
}

__global__ __launch_bounds__(256, 1)
void gemm_mma3(const __nv_bfloat16* __restrict__ Ah, const __nv_bfloat16* __restrict__ Al,
               const __nv_bfloat16* __restrict__ Bh, const __nv_bfloat16* __restrict__ Bl,
               const float* __restrict__ resid, float* __restrict__ Cf,
               __nv_bfloat16* __restrict__ O0h, __nv_bfloat16* __restrict__ O0l,
               __nv_bfloat16* __restrict__ O1h, __nv_bfloat16* __restrict__ O1l,
               __nv_bfloat16* __restrict__ O2h, __nv_bfloat16* __restrict__ O2l)
{
    extern __shared__ __align__(128) char smem[];
    const uint32_t sb = smem_u32(smem);
    const int tid = threadIdx.x, wid = tid >> 5, lane = tid & 31;
    const int warp_m = wid & 3;
    const int warp_n = wid >> 2;
    const int n0 = blockIdx.x * TILE_N;
    const int m0 = blockIdx.y * TILE_M;

    float acc[2][8][4];
#pragma unroll
    for (int mt = 0; mt < 2; mt++)
#pragma unroll
        for (int nt = 0; nt < 8; nt++)
#pragma unroll
            for (int i = 0; i < 4; i++) acc[mt][nt][i] = 0.f;

    gemm_loads(sb, tid, 0, m0, n0, Ah, Al, Bh, Bl);
    gemm_loads(sb + STAGE_BYTES, tid, 1, m0, n0, Ah, Al, Bh, Bl);
    cp_wait<1>();
    __syncthreads();

    const int arow = warp_m * 32 + (lane & 15);
    const uint32_t acolb = (uint32_t)((lane >> 4) << 4);
    const int brow = warp_n * 64 + ((lane >> 4) << 3) + (lane & 7);
    const uint32_t bcolb = (uint32_t)(((lane >> 3) & 1) << 4);

    for (int it = 0; it < NITER; it++) {
        if (it + 2 < NITER)
            gemm_loads(sb + ((it + 2) % 3) * STAGE_BYTES, tid, it + 2, m0, n0, Ah, Al, Bh, Bl);

        const uint32_t s0 = sb + (it % 3) * STAGE_BYTES;
#pragma unroll
        for (int ks = 0; ks < 4; ks++) {
            const uint32_t kb = (uint32_t)(ks * 32);
            uint32_t ah[2][4], al[2][4];
#pragma unroll
            for (int mt = 0; mt < 2; mt++) {
                const uint32_t off = SW128((uint32_t)((arow + mt * 16) * 128) + kb + acolb);
                ldsm4(ah[mt], s0 + OFF_AH + off);
                ldsm4(al[mt], s0 + OFF_AL + off);
            }
            uint32_t bh[4][4], bl[4][4];
#pragma unroll
            for (int p = 0; p < 4; p++) {
                const uint32_t off = SW128((uint32_t)((brow + p * 16) * 128) + kb + bcolb);
                ldsm4(bh[p], s0 + OFF_BH + off);
                ldsm4(bl[p], s0 + OFF_BL + off);
            }
#pragma unroll
            for (int mt = 0; mt < 2; mt++)
#pragma unroll
                for (int p = 0; p < 4; p++)
#pragma unroll
                    for (int hf = 0; hf < 2; hf++) {
                        float* c = acc[mt][p * 2 + hf];
                        mma_bf16(c, ah[mt], bh[p][hf * 2], bh[p][hf * 2 + 1]);
                        mma_bf16(c, ah[mt], bl[p][hf * 2], bl[p][hf * 2 + 1]);
                        mma_bf16(c, al[mt], bh[p][hf * 2], bh[p][hf * 2 + 1]);
                    }
        }

        if (it + 2 < NITER) cp_wait<1>(); else cp_wait<0>();
        __syncthreads();
    }

    const int sel = n0 >> 10;
    const int nl = n0 & (D_DIM - 1);
    __nv_bfloat16* Oh = (sel == 0) ? O0h : (sel == 1) ? O1h : O2h;
    __nv_bfloat16* Ol = (sel == 0) ? O0l : (sel == 1) ? O1l : O2l;
#pragma unroll
    for (int mt = 0; mt < 2; mt++) {
        const int row0 = m0 + warp_m * 32 + mt * 16 + (lane >> 2);
#pragma unroll
        for (int nt = 0; nt < 8; nt++) {
            const int coll = nl + warp_n * 64 + nt * 8 + (lane & 3) * 2;
            const float* c = acc[mt][nt];
            const size_t off = (size_t)row0 * D_DIM + coll;
            if (Cf) {
                float2 v0 = make_float2(c[0], c[1]);
                float2 v1 = make_float2(c[2], c[3]);
                if (resid) {
                    const float2 r0 = *(const float2*)&resid[off];
                    const float2 r1 = *(const float2*)&resid[off + 8 * D_DIM];
                    v0.x += r0.x; v0.y += r0.y; v1.x += r1.x; v1.y += r1.y;
                }
                *(float2*)&Cf[off] = v0;
                *(float2*)&Cf[off + 8 * D_DIM] = v1;
            } else {
                uint32_t hp, lp;
                split_pack(c[0], c[1], hp, lp);
                *(uint32_t*)&Oh[off] = hp; *(uint32_t*)&Ol[off] = lp;
                split_pack(c[2], c[3], hp, lp);
                *(uint32_t*)&Oh[off + 8 * D_DIM] = hp; *(uint32_t*)&Ol[off + 8 * D_DIM] = lp;
            }
        }
    }
}

// ---------------------------------------------------------------------------
// Tensor-core flash attention. R11: 64 q-rows / 128 threads / 4 warps per CTA,
// 2 CTAs per SM (regs 238*128*2 < 64K; smem 112KB*2 = 224KB <= 228KB) so one
// CTA's softmax overlaps the other's mma bursts. Per-warp workload identical
// to R10. smem: Qh 8K | Ql 8K | 3 stages x {Kh,Kl,Vh,Vl 8K each} = 112KB.
// ---------------------------------------------------------------------------
#define ATT_SMEM (16384 + 3 * 32768)   // 114688
#define SLOG2E 0.1803368801111204f     // 0.125 * log2(e)
#define NKV (S_LEN / 64)               // 32

__device__ __forceinline__ void attn_kv_load(
    uint32_t sbase, int tid, size_t kvbase, int k0,
    const __nv_bfloat16* kh, const __nv_bfloat16* kl,
    const __nv_bfloat16* vh, const __nv_bfloat16* vl)
{
#pragma unroll
    for (int c = tid; c < 512; c += 128) {
        const int row = c >> 3, ch = c & 7;
        const uint32_t sw = SW128((uint32_t)(row * 128 + ch * 16));
        const size_t g = kvbase + (size_t)(k0 + row) * D_DIM + ch * 8;
        cpa16(sbase + sw, kh + g);
        cpa16(sbase + 8192 + sw, kl + g);
        cpa16(sbase + 16384 + sw, vh + g);
        cpa16(sbase + 24576 + sw, vl + g);
    }
    CP_COMMIT();
}

__global__ __launch_bounds__(128, 2)
void attn_mma(const __nv_bfloat16* __restrict__ qh, const __nv_bfloat16* __restrict__ ql,
              const __nv_bfloat16* __restrict__ kh, const __nv_bfloat16* __restrict__ kl,
              const __nv_bfloat16* __restrict__ vh, const __nv_bfloat16* __restrict__ vl,
              __nv_bfloat16* __restrict__ zh, __nv_bfloat16* __restrict__ zl)
{
    extern __shared__ __align__(128) char smem[];
    const uint32_t sb = smem_u32(smem);
    const int tid = threadIdx.x, wid = tid >> 5, lane = tid & 31;
    const int q0 = blockIdx.x * 64;
    const int h = blockIdx.y, b = blockIdx.z;
    const size_t qbase = ((size_t)(b * S_LEN + q0)) * D_DIM + h * DH;
    const size_t kvbase = ((size_t)b * S_LEN) * D_DIM + h * DH;

    // prologue: Q (64 rows, hi+lo) then kv stages 0,1
#pragma unroll
    for (int c = tid; c < 512; c += 128) {
        const int row = c >> 3, ch = c & 7;
        const uint32_t sw = SW128((uint32_t)(row * 128 + ch * 16));
        const size_t g = qbase + (size_t)row * D_DIM + ch * 8;
        cpa16(sb + sw, qh + g);
        cpa16(sb + 8192 + sw, ql + g);
    }
    CP_COMMIT();
    attn_kv_load(sb + 16384, tid, kvbase, 0, kh, kl, vh, vl);
    attn_kv_load(sb + 16384 + 32768, tid, kvbase, 64, kh, kl, vh, vl);
    cp_wait<1>();          // Q + kv0 complete
    __syncthreads();

    const int arow = wid * 16 + (lane & 15);
    const uint32_t acolb = (uint32_t)((lane >> 4) << 4);
    const int bnrow = ((lane >> 4) << 3) + (lane & 7);
    const uint32_t bncol = (uint32_t)(((lane >> 3) & 1) << 4);
    const int vrow = ((lane >> 3) & 1) * 8 + (lane & 7);
    const uint32_t vcolb = (uint32_t)((lane >> 4) << 4);

    // Q fragments (constant across kv tiles)
    uint32_t qfh[4][4], qfl[4][4];
#pragma unroll
    for (int ks = 0; ks < 4; ks++) {
        const uint32_t off = SW128((uint32_t)(arow * 128) + (uint32_t)(ks * 32) + acolb);
        ldsm4(qfh[ks], sb + off);
        ldsm4(qfl[ks], sb + 8192 + off);
    }

    float O[8][4];
#pragma unroll
    for (int nt = 0; nt < 8; nt++)
#pragma unroll
        for (int i = 0; i < 4; i++) O[nt][i] = 0.f;
    float m0 = -1.0e30f, m1 = -1.0e30f, l0 = 0.f, l1 = 0.f;

    for (int t = 0; t < NKV; t++) {
        if (t + 2 < NKV)
            attn_kv_load(sb + 16384 + ((t + 2) % 3) * 32768, tid, kvbase, (t + 2) * 64, kh, kl, vh, vl);

        const uint32_t kbB = sb + 16384 + (t % 3) * 32768;

        // ---- S = Q K^T (split 3-mma), fp32 accum
        float S[8][4];
#pragma unroll
        for (int nt = 0; nt < 8; nt++)
#pragma unroll
            for (int i = 0; i < 4; i++) S[nt][i] = 0.f;
#pragma unroll
        for (int ks = 0; ks < 4; ks++) {
            uint32_t bh_[4][4], bl_[4][4];
#pragma unroll
            for (int p = 0; p < 4; p++) {
                const uint32_t off = SW128((uint32_t)((p * 16 + bnrow) * 128) + (uint32_t)(ks * 32) + bncol);
                ldsm4(bh_[p], kbB + off);
                ldsm4(bl_[p], kbB + 8192 + off);
            }
#pragma unroll
            for (int p = 0; p < 4; p++)
#pragma unroll
                for (int hf = 0; hf < 2; hf++) {
                    float* c = S[p * 2 + hf];
                    mma_bf16(c, qfh[ks], bh_[p][hf * 2], bh_[p][hf * 2 + 1]);
                    mma_bf16(c, qfh[ks], bl_[p][hf * 2], bl_[p][hf * 2 + 1]);
                    mma_bf16(c, qfl[ks], bh_[p][hf * 2], bh_[p][hf * 2 + 1]);
                }
        }

        // ---- online softmax (all-MUFU; scale folded into exp arg)
        float mx0 = -1.0e30f, mx1 = -1.0e30f;
#pragma unroll
        for (int nt = 0; nt < 8; nt++) {
            mx0 = fmaxf(mx0, fmaxf(S[nt][0], S[nt][1]));
            mx1 = fmaxf(mx1, fmaxf(S[nt][2], S[nt][3]));
        }
        mx0 = fmaxf(mx0, __shfl_xor_sync(0xffffffffu, mx0, 1));
        mx0 = fmaxf(mx0, __shfl_xor_sync(0xffffffffu, mx0, 2));
        mx1 = fmaxf(mx1, __shfl_xor_sync(0xffffffffu, mx1, 1));
        mx1 = fmaxf(mx1, __shfl_xor_sync(0xffffffffu, mx1, 2));
        const float mn0 = fmaxf(m0, mx0), mn1 = fmaxf(m1, mx1);
        const float mb0 = mn0 * SLOG2E, mb1 = mn1 * SLOG2E;
        const float a0 = ex2_mufu(fmaf(m0, SLOG2E, -mb0));
        const float a1 = ex2_mufu(fmaf(m1, SLOG2E, -mb1));
        m0 = mn0; m1 = mn1;

        float s0 = 0.f, s1 = 0.f;
#pragma unroll
        for (int nt = 0; nt < 8; nt++) {
            S[nt][0] = ex2_mufu(fmaf(S[nt][0], SLOG2E, -mb0));
            S[nt][1] = ex2_mufu(fmaf(S[nt][1], SLOG2E, -mb0));
            S[nt][2] = ex2_mufu(fmaf(S[nt][2], SLOG2E, -mb1));
            S[nt][3] = ex2_mufu(fmaf(S[nt][3], SLOG2E, -mb1));
            s0 += S[nt][0] + S[nt][1];
            s1 += S[nt][2] + S[nt][3];
        }
        l0 = l0 * a0 + s0;
        l1 = l1 * a1 + s1;

        if (__ballot_sync(0xffffffffu, (a0 != 1.0f) || (a1 != 1.0f))) {
#pragma unroll
            for (int nt = 0; nt < 8; nt++) {
                O[nt][0] *= a0; O[nt][1] *= a0; O[nt][2] *= a1; O[nt][3] *= a1;
            }
        }

        // ---- P fragments in registers
        uint32_t pfh[4][4], pfl[4][4];
#pragma unroll
        for (int ks = 0; ks < 4; ks++) {
            split_pack(S[2 * ks][0], S[2 * ks][1], pfh[ks][0], pfl[ks][0]);
            split_pack(S[2 * ks][2], S[2 * ks][3], pfh[ks][1], pfl[ks][1]);
            split_pack(S[2 * ks + 1][0], S[2 * ks + 1][1], pfh[ks][2], pfl[ks][2]);
            split_pack(S[2 * ks + 1][2], S[2 * ks + 1][3], pfh[ks][3], pfl[ks][3]);
        }

        // ---- O += P V (split 3-mma)
#pragma unroll
        for (int ks = 0; ks < 4; ks++) {
            uint32_t vh_[4][4], vl_[4][4];
#pragma unroll
            for (int p = 0; p < 4; p++) {
                const uint32_t off = SW128((uint32_t)((ks * 16 + vrow) * 128) + (uint32_t)(p * 32) + vcolb);
                ldsm4t(vh_[p], kbB + 16384 + off);
                ldsm4t(vl_[p], kbB + 24576 + off);
            }
#pragma unroll
            for (int p = 0; p < 4; p++)
#pragma unroll
                for (int hf = 0; hf < 2; hf++) {
                    float* o = O[p * 2 + hf];
                    mma_bf16(o, pfh[ks], vh_[p][hf * 2], vh_[p][hf * 2 + 1]);
                    mma_bf16(o, pfh[ks], vl_[p][hf * 2], vl_[p][hf * 2 + 1]);
                    mma_bf16(o, pfl[ks], vh_[p][hf * 2], vh_[p][hf * 2 + 1]);
                }
        }

        if (t + 2 < NKV) cp_wait<1>(); else cp_wait<0>();
        __syncthreads();
    }

    // ---- epilogue
    l0 += __shfl_xor_sync(0xffffffffu, l0, 1);
    l0 += __shfl_xor_sync(0xffffffffu, l0, 2);
    l1 += __shfl_xor_sync(0xffffffffu, l1, 1);
    l1 += __shfl_xor_sync(0xffffffffu, l1, 2);
    const float inv0 = 1.0f / l0, inv1 = 1.0f / l1;

    const int rowg = b * S_LEN + q0 + wid * 16 + (lane >> 2);
#pragma unroll
    for (int nt = 0; nt < 8; nt++) {
        const int col = h * DH + nt * 8 + (lane & 3) * 2;
        uint32_t hp, lp;
        split_pack(O[nt][0] * inv0, O[nt][1] * inv0, hp, lp);
        size_t off = (size_t)rowg * D_DIM + col;
        *(uint32_t*)&zh[off] = hp; *(uint32_t*)&zl[off] = lp;
        split_pack(O[nt][2] * inv1, O[nt][3] * inv1, hp, lp);
        off += (size_t)8 * D_DIM;
        *(uint32_t*)&zh[off] = hp; *(uint32_t*)&zl[off] = lp;
    }
}

// ---------------------------------------------------------------------------
// Inputs (metadata order): x, mask(bool, unused), Wq, Wk, Wv, Wout
// ---------------------------------------------------------------------------
extern "C" void kernel_launch(void* const* d_in, const int* in_sizes, int n_in,
                              void* d_out, int out_size)
{
    (void)in_sizes; (void)n_in; (void)out_size;
    const float* x    = (const float*)d_in[0];
    const float* Wq   = (const float*)d_in[2];
    const float* Wk   = (const float*)d_in[3];
    const float* Wv   = (const float*)d_in[4];
    const float* Wout = (const float*)d_in[5];
    float* out = (float*)d_out;

    __nv_bfloat16 *xh, *xl, *qh, *ql, *kh, *kl, *vh, *vl, *zh, *zl, *wth, *wtl;
    cudaGetSymbolAddress((void**)&xh, g_xh);
    cudaGetSymbolAddress((void**)&xl, g_xl);
    cudaGetSymbolAddress((void**)&qh, g_qh);
    cudaGetSymbolAddress((void**)&ql, g_ql);
    cudaGetSymbolAddress((void**)&kh, g_kh);
    cudaGetSymbolAddress((void**)&kl, g_kl);
    cudaGetSymbolAddress((void**)&vh, g_vh);
    cudaGetSymbolAddress((void**)&vl, g_vl);
    cudaGetSymbolAddress((void**)&zh, g_zh);
    cudaGetSymbolAddress((void**)&zl, g_zl);
    cudaGetSymbolAddress((void**)&wth, g_wth);
    cudaGetSymbolAddress((void**)&wtl, g_wtl);

    const int NW = D_DIM * D_DIM;

    // 1) split x; transpose+split all 4 weights in one launch
    k_split<<<(MROWS * D_DIM + 255) / 256, 256>>>(x, xh, xl, MROWS * D_DIM);
    k_tsplit4<<<dim3(D_DIM / 32, D_DIM / 32, 4), dim3(32, 8)>>>(Wq, Wk, Wv, Wout, wth, wtl);

    // 2) merged QKV projection (N=3072)
    cudaFuncSetAttribute(gemm_mma3, cudaFuncAttributeMaxDynamicSharedMemorySize, GEMM_SMEM);
    gemm_mma3<<<dim3(3 * D_DIM / TILE_N, MROWS / TILE_M), 256, GEMM_SMEM>>>(
        xh, xl, wth, wtl, nullptr, nullptr, qh, ql, kh, kl, vh, vl);

    // 3) tensor-core flash attention (64-row CTAs, 2 CTAs/SM) -> zh/zl
    cudaFuncSetAttribute(attn_mma, cudaFuncAttributeMaxDynamicSharedMemorySize, ATT_SMEM);
    attn_mma<<<dim3(S_LEN / 64, H_NUM, B_NUM), 128, ATT_SMEM>>>(qh, ql, kh, kl, vh, vl, zh, zl);

    // 4) output projection + residual -> fp32 out
    gemm_mma3<<<dim3(D_DIM / TILE_N, MROWS / TILE_M), 256, GEMM_SMEM>>>(
        zh, zl, wth + 3 * (size_t)NW, wtl + 3 * (size_t)NW, x, out,
        nullptr, nullptr, nullptr, nullptr, nullptr, nullptr);
}